// round 14
// baseline (speedup 1.0000x reference)
#include <cuda_runtime.h>
#include <cuda_fp16.h>
#include <cstdint>

#define SEQ  2048
#define DM   1024
#define NH   16
#define HDIM 64
#define FFD  4096
#define NQKV 3072

// ---------------- scratch (no allocations allowed) ----------------
__device__ __half g_Xsp[(size_t)SEQ * DM];      // hi plane only
__device__ __half g_Wqkvt[2u * NQKV * DM];
__device__ __half g_Wpt[(size_t)DM * DM];       // hi plane only
__device__ __half g_W1t[(size_t)FFD * DM];      // hi plane only
__device__ __half g_W2t[(size_t)DM * FFD];      // hi plane only
__device__ __half g_Qsp[NH * SEQ * HDIM];       // hi plane only
__device__ __half g_Ksp[NH * SEQ * HDIM];       // hi plane only
__device__ float  g_Vf[NH * SEQ * HDIM];
__device__ __half g_Vn[NH * HDIM * SEQ];        // hi plane only
__device__ float  g_Z[NH * SEQ];
__device__ __half g_Csp[(size_t)SEQ * DM];      // hi plane only
__device__ __half g_Projsp[(size_t)SEQ * DM];   // hi plane only
__device__ __half g_Hsp[(size_t)SEQ * FFD];     // hi plane only

// ---------------- helpers ----------------
__device__ __forceinline__ void split_h(float a, __half& h, __half& l) {
    h = __float2half_rn(a);
    l = __float2half_rn(a - __half2float(h));
}
__device__ __forceinline__ uint32_t pkh(__half a, __half b) {
    __half2 t(a, b);
    return *reinterpret_cast<uint32_t*>(&t);
}
__device__ __forceinline__ void ldsm4(uint32_t& r0, uint32_t& r1, uint32_t& r2, uint32_t& r3, uint32_t a) {
    asm volatile("ldmatrix.sync.aligned.m8n8.x4.shared.b16 {%0,%1,%2,%3}, [%4];"
                 : "=r"(r0), "=r"(r1), "=r"(r2), "=r"(r3) : "r"(a));
}
__device__ __forceinline__ void mma_h(float c[4], const uint32_t a[4], const uint32_t b[2]) {
    asm volatile(
        "mma.sync.aligned.m16n8k16.row.col.f32.f16.f16.f32 "
        "{%0,%1,%2,%3}, {%4,%5,%6,%7}, {%8,%9}, {%0,%1,%2,%3};"
        : "+f"(c[0]), "+f"(c[1]), "+f"(c[2]), "+f"(c[3])
        : "r"(a[0]), "r"(a[1]), "r"(a[2]), "r"(a[3]), "r"(b[0]), "r"(b[1]));
}
__device__ __forceinline__ void cp16(uint32_t dst, const void* src) {
    asm volatile("cp.async.cg.shared.global [%0], [%1], 16;" :: "r"(dst), "l"(src));
}
__device__ __forceinline__ void cp_commit() {
    asm volatile("cp.async.commit_group;" ::: "memory");
}
template <int N>
__device__ __forceinline__ void cp_wait() {
    asm volatile("cp.async.wait_group %0;" :: "n"(N) : "memory");
}

// =====================================================================
// fp16 split mma.sync GEMM.  CTA 128(M) x 32*NW2(N), BK=32.
// ANP/BNP: number of A/B fp16 planes.
// EPI: 0 fp32+bias, 4 QKV scatter (Q/K hi-only, V fp32),
//      5 fp16 hi-only out+bias(+relu), 6 exp -> col-Z atomics (no store).
// =====================================================================
template <int EPI, int ANP, int BNP, int RELU, int SKBITS, int NW2>
__global__ void __launch_bounds__(NW2 * 64, (NW2 == 2) ? 3 : 2)
gg(const __half* __restrict__ A, const __half* __restrict__ B,
   const float* __restrict__ bias, const float* __restrict__ bias2,
   const float* __restrict__ bias3, void* __restrict__ Cv,
   float* __restrict__ Zb,
   int K, int lda, int ldb, int ldc,
   size_t aZ, size_t bZ, size_t cZ, size_t pA, size_t pB, size_t pC,
   float scale)
{
    constexpr int T     = NW2 * 64;
    constexpr int BNT   = 32 * NW2;
    constexpr int ASEG_ = 10240;
    constexpr int BSEG_ = BNT * 80;
    constexpr int STG   = ANP * ASEG_ + BNP * BSEG_;
    constexpr int CA    = 512 / T;

    extern __shared__ __align__(16) unsigned char sm[];
    const uint32_t smb = (uint32_t)__cvta_generic_to_shared(sm);

    const int tid = threadIdx.x;
    const int warp = tid >> 5, lane = tid & 31;
    const int g = lane >> 2, tg = lane & 3;
    const int b3 = (lane >> 3) & 1, b4 = (lane >> 4) & 1;
    const int m0 = (warp & 1) * 64, n0 = (warp >> 1) * 32;

    const int z = blockIdx.z;
    const int zhead = z >> SKBITS;
    const int bm = blockIdx.y * 128;
    const int bn = blockIdx.x * BNT;

    const __half* Ag = A + zhead * aZ;
    const __half* Bg = B + zhead * bZ;

    uint32_t aOff[4], bOff[2];
    #pragma unroll
    for (int tm = 0; tm < 4; tm++)
        aOff[tm] = ((m0 + tm * 16 + (lane & 7) + b3 * 8) * 40 + b4 * 8) * 2;
    #pragma unroll
    for (int q = 0; q < 2; q++)
        bOff[q] = ((n0 + q * 16 + (lane & 7) + b4 * 8) * 40 + b3 * 8) * 2;

    auto ldgsts = [&](int st, int slab) {
        const int k0 = slab << 5;
        #pragma unroll
        for (int p = 0; p < ANP; p++)
            #pragma unroll
            for (int j = 0; j < CA; j++) {
                int idx = tid + j * T;
                int row = idx >> 2, kc = idx & 3;
                cp16(smb + st * STG + p * ASEG_ + row * 80 + kc * 16,
                     Ag + p * pA + (size_t)(bm + row) * lda + k0 + kc * 8);
            }
        #pragma unroll
        for (int p = 0; p < BNP; p++)
            #pragma unroll
            for (int j = 0; j < 2; j++) {
                int idx = tid + j * T;
                int row = idx >> 2, kc = idx & 3;
                cp16(smb + st * STG + ANP * ASEG_ + p * BSEG_ + row * 80 + kc * 16,
                     Bg + p * pB + (size_t)(bn + row) * ldb + k0 + kc * 8);
            }
        cp_commit();
    };

    float acc[4][4][4];
    #pragma unroll
    for (int tm = 0; tm < 4; tm++)
        #pragma unroll
        for (int tn = 0; tn < 4; tn++)
            #pragma unroll
            for (int r = 0; r < 4; r++) acc[tm][tn][r] = 0.f;

    const int ns = K >> 5;
    ldgsts(0, 0);
    ldgsts(1, 1);
    cp_wait<1>();
    __syncthreads();

    for (int i = 0; i < ns; i++) {
        const int buf = i & 1;
        const uint32_t aB = smb + buf * STG;
        const uint32_t bB = smb + buf * STG + ANP * ASEG_;
        #pragma unroll
        for (int ks = 0; ks < 2; ks++) {
            uint32_t af[4][ANP][4], bf[BNP][4][2];
            #pragma unroll
            for (int tm = 0; tm < 4; tm++)
                #pragma unroll
                for (int p = 0; p < ANP; p++)
                    ldsm4(af[tm][p][0], af[tm][p][1], af[tm][p][2], af[tm][p][3],
                          aB + p * ASEG_ + aOff[tm] + ks * 32);
            #pragma unroll
            for (int p = 0; p < BNP; p++)
                #pragma unroll
                for (int q = 0; q < 2; q++) {
                    uint32_t r0, r1, r2, r3;
                    ldsm4(r0, r1, r2, r3, bB + p * BSEG_ + bOff[q] + ks * 32);
                    bf[p][q * 2 + 0][0] = r0; bf[p][q * 2 + 0][1] = r1;
                    bf[p][q * 2 + 1][0] = r2; bf[p][q * 2 + 1][1] = r3;
                }
            #pragma unroll
            for (int tm = 0; tm < 4; tm++)
                #pragma unroll
                for (int tn = 0; tn < 4; tn++) {
                    mma_h(acc[tm][tn], af[tm][0], bf[0][tn]);
                    if (BNP == 2) mma_h(acc[tm][tn], af[tm][0], bf[1][tn]);
                    if (ANP == 2) mma_h(acc[tm][tn], af[tm][1], bf[0][tn]);
                }
        }
        __syncthreads();
        if (i + 2 < ns) ldgsts(buf, i + 2);
        if (i + 1 < ns) {
            if (i + 2 < ns) cp_wait<1>(); else cp_wait<0>();
            __syncthreads();
        }
    }

    // ------------------ epilogues ------------------
    if (EPI == 6) {
        float cs[4][2];
        #pragma unroll
        for (int tn = 0; tn < 4; tn++) { cs[tn][0] = 0.f; cs[tn][1] = 0.f; }
        #pragma unroll
        for (int tm = 0; tm < 4; tm++)
            #pragma unroll
            for (int half = 0; half < 2; half++)
                #pragma unroll
                for (int tn = 0; tn < 4; tn++) {
                    cs[tn][0] += __expf(acc[tm][tn][half * 2 + 0] * scale);
                    cs[tn][1] += __expf(acc[tm][tn][half * 2 + 1] * scale);
                }
        float* Zp = Zb + (size_t)zhead * SEQ;
        #pragma unroll
        for (int tn = 0; tn < 4; tn++)
            #pragma unroll
            for (int j = 0; j < 2; j++) {
                float v = cs[tn][j];
                v += __shfl_xor_sync(0xffffffffu, v, 4);
                v += __shfl_xor_sync(0xffffffffu, v, 8);
                v += __shfl_xor_sync(0xffffffffu, v, 16);
                if (lane < 4) atomicAdd(Zp + bn + n0 + tn * 8 + 2 * tg + j, v);
            }
    } else if (EPI == 4) {
        #pragma unroll
        for (int tn = 0; tn < 4; tn++) {
            const int eg  = bn + n0 + tn * 8 + 2 * tg;
            const int seg = eg >> 10;
            const int hh  = (eg >> 6) & 15;
            const int e   = eg & 63;
            const float* bsel = (seg == 0) ? bias : (seg == 1) ? bias2 : bias3;
            float2 bb = *(const float2*)(bsel + hh * 64 + e);
            #pragma unroll
            for (int tm = 0; tm < 4; tm++)
                #pragma unroll
                for (int half = 0; half < 2; half++) {
                    const int row = bm + m0 + tm * 16 + g + half * 8;
                    float vx = acc[tm][tn][half * 2 + 0] + bb.x;
                    float vy = acc[tm][tn][half * 2 + 1] + bb.y;
                    if (seg == 2) {
                        *(float2*)(g_Vf + ((size_t)hh * SEQ + row) * HDIM + e) =
                            make_float2(vx, vy);
                    } else {
                        __half* O = (seg == 0) ? g_Qsp : g_Ksp;
                        size_t base = (size_t)hh * SEQ * HDIM + (size_t)row * HDIM + e;
                        *(uint32_t*)(O + base) =
                            pkh(__float2half_rn(vx), __float2half_rn(vy));
                    }
                }
        }
    } else if (EPI == 5) {
        __half* Ch = (__half*)Cv + zhead * cZ;
        #pragma unroll
        for (int tn = 0; tn < 4; tn++) {
            const int col = bn + n0 + tn * 8 + 2 * tg;
            float2 bb = *(const float2*)(bias + col);
            #pragma unroll
            for (int tm = 0; tm < 4; tm++)
                #pragma unroll
                for (int half = 0; half < 2; half++) {
                    const int row = bm + m0 + tm * 16 + g + half * 8;
                    float vx = acc[tm][tn][half * 2 + 0] + bb.x;
                    float vy = acc[tm][tn][half * 2 + 1] + bb.y;
                    if (RELU) { vx = fmaxf(vx, 0.f); vy = fmaxf(vy, 0.f); }
                    *(uint32_t*)(Ch + (size_t)row * ldc + col) =
                        pkh(__float2half_rn(vx), __float2half_rn(vy));
                }
        }
    } else {
        float* C = (float*)Cv + zhead * cZ;
        #pragma unroll
        for (int tn = 0; tn < 4; tn++) {
            const int col = bn + n0 + tn * 8 + 2 * tg;
            float2 bb = *(const float2*)(bias + col);
            #pragma unroll
            for (int tm = 0; tm < 4; tm++)
                #pragma unroll
                for (int half = 0; half < 2; half++) {
                    const int row = bm + m0 + tm * 16 + g + half * 8;
                    *(float2*)(C + (size_t)row * ldc + col) =
                        make_float2(acc[tm][tn][half * 2 + 0] + bb.x,
                                    acc[tm][tn][half * 2 + 1] + bb.y);
                }
        }
    }
}

// =====================================================================
// Fused attention (hi-only): O[t, h*64+e] = sum_s exp(Khi[t].Qhi[s]/8) Vhi[e,s]
// Per CTA: 64 t-rows (4 warps x 16 rows), one head; s in 32-slabs,
// double-buffered.  smem: K 2x5120 | stage{0,1}: Q 5120 | V 5120.
// Output: Csp hi plane only.
// =====================================================================
#define FAV_SMEM 30720

__global__ void __launch_bounds__(128, 4)
fav(const __half* __restrict__ Qsp, const __half* __restrict__ Ksp,
    const __half* __restrict__ Vn, __half* __restrict__ Csp)
{
    extern __shared__ __align__(16) unsigned char sm[];
    const uint32_t smb = (uint32_t)__cvta_generic_to_shared(sm);

    const int tid = threadIdx.x;
    const int warp = tid >> 5, lane = tid & 31;
    const int g = lane >> 2, tg = lane & 3;
    const int b3 = (lane >> 3) & 1, b4 = (lane >> 4) & 1;
    const int m0 = warp * 16;

    const int bt = blockIdx.x * 64;
    const int h  = blockIdx.y;

    const __half* Kh = Ksp + (size_t)h * SEQ * HDIM;
    const __half* Qh = Qsp + (size_t)h * SEQ * HDIM;
    const __half* Vh = Vn + (size_t)h * HDIM * SEQ;

    const uint32_t aOffK = ((m0 + (lane & 7) + b3 * 8) * 40 + b4 * 8) * 2;
    uint32_t bOffQ[2], bOffV[4];
    #pragma unroll
    for (int q = 0; q < 2; q++)
        bOffQ[q] = ((q * 16 + (lane & 7) + b4 * 8) * 40 + b3 * 8) * 2;
    #pragma unroll
    for (int q = 0; q < 4; q++)
        bOffV[q] = ((q * 16 + (lane & 7) + b4 * 8) * 40 + b3 * 8) * 2;

    // ---- K tile (once): 2 kslabs x [64 rows x 80B] ----
    #pragma unroll
    for (int j = 0; j < 4; j++) {
        int idx = tid + j * 128;
        int slab = idx >> 8;
        int r = (idx & 255) >> 2;
        int c = idx & 3;
        cp16(smb + slab * 5120 + r * 80 + c * 16,
             Kh + (size_t)(bt + r) * HDIM + slab * 32 + c * 8);
    }
    cp_commit();

    auto ldStage = [&](int st, int s0) {
        const uint32_t base = smb + 10240 + st * 10240;
        #pragma unroll
        for (int j = 0; j < 2; j++) {            // Q: 2 kslabs x [32 x 80B]
            int idx = tid + j * 128;
            int ksl = idx >> 7;
            int r = (idx & 127) >> 2;
            int c = idx & 3;
            cp16(base + ksl * 2560 + r * 80 + c * 16,
                 Qh + (size_t)(s0 + r) * HDIM + ksl * 32 + c * 8);
        }
        #pragma unroll
        for (int j = 0; j < 2; j++) {            // V: [64 e x 80B]
            int idx = tid + j * 128;
            int e = idx >> 2;
            int c = idx & 3;
            cp16(base + 5120 + e * 80 + c * 16,
                 Vh + (size_t)e * SEQ + s0 + c * 8);
        }
        cp_commit();
    };

    float O[8][4];
    #pragma unroll
    for (int tn = 0; tn < 8; tn++)
        #pragma unroll
        for (int r = 0; r < 4; r++) O[tn][r] = 0.f;

    const int ns = SEQ / 32;
    ldStage(0, 0);
    ldStage(1, 32);
    cp_wait<1>();
    __syncthreads();

    for (int i = 0; i < ns; i++) {
        const int buf = i & 1;
        const uint32_t stg = smb + 10240 + buf * 10240;

        // ---- MMA1: S[64 x 32] = Khi . Qhi  (16 rows per warp) ----
        float S[4][4];
        #pragma unroll
        for (int tn = 0; tn < 4; tn++)
            #pragma unroll
            for (int r = 0; r < 4; r++) S[tn][r] = 0.f;

        #pragma unroll
        for (int kk = 0; kk < 4; kk++) {
            const int j = kk >> 1, ksl = kk & 1;
            uint32_t aK[4], bq[4][2];
            ldsm4(aK[0], aK[1], aK[2], aK[3],
                  smb + j * 5120 + aOffK + ksl * 32);
            #pragma unroll
            for (int q = 0; q < 2; q++) {
                uint32_t r0, r1, r2, r3;
                ldsm4(r0, r1, r2, r3, stg + j * 2560 + bOffQ[q] + ksl * 32);
                bq[q * 2 + 0][0] = r0; bq[q * 2 + 0][1] = r1;
                bq[q * 2 + 1][0] = r2; bq[q * 2 + 1][1] = r3;
            }
            #pragma unroll
            for (int tn = 0; tn < 4; tn++)
                mma_h(S[tn], aK, bq[tn]);
        }

        // ---- exp + MMA2: O += P . Vhi ----
        #pragma unroll
        for (int kk2 = 0; kk2 < 2; kk2++) {
            uint32_t pa[4];
            const int nt0 = 2 * kk2, nt1 = nt0 + 1;
            pa[0] = pkh(__float2half_rn(__expf(S[nt0][0] * 0.125f)),
                        __float2half_rn(__expf(S[nt0][1] * 0.125f)));
            pa[1] = pkh(__float2half_rn(__expf(S[nt0][2] * 0.125f)),
                        __float2half_rn(__expf(S[nt0][3] * 0.125f)));
            pa[2] = pkh(__float2half_rn(__expf(S[nt1][0] * 0.125f)),
                        __float2half_rn(__expf(S[nt1][1] * 0.125f)));
            pa[3] = pkh(__float2half_rn(__expf(S[nt1][2] * 0.125f)),
                        __float2half_rn(__expf(S[nt1][3] * 0.125f)));
            #pragma unroll
            for (int q = 0; q < 4; q++) {
                uint32_t r0, r1, r2, r3;
                ldsm4(r0, r1, r2, r3, stg + 5120 + bOffV[q] + kk2 * 32);
                uint32_t bv0[2] = {r0, r1};
                uint32_t bv1[2] = {r2, r3};
                mma_h(O[q * 2 + 0], pa, bv0);
                mma_h(O[q * 2 + 1], pa, bv1);
            }
        }

        __syncthreads();
        if (i + 2 < ns) ldStage(buf, (i + 2) * 32);
        if (i + 1 < ns) {
            if (i + 2 < ns) cp_wait<1>(); else cp_wait<0>();
            __syncthreads();
        }
    }

    // ---- epilogue: Csp hi plane only, col = h*64 + e ----
    #pragma unroll
    for (int tn = 0; tn < 8; tn++) {
        const int col = h * 64 + tn * 8 + 2 * tg;
        #pragma unroll
        for (int half = 0; half < 2; half++) {
            const int row = bt + m0 + g + half * 8;
            *(uint32_t*)(Csp + (size_t)row * DM + col) =
                pkh(__float2half_rn(O[tn][half * 2 + 0]),
                    __float2half_rn(O[tn][half * 2 + 1]));
        }
    }
}

// =====================================================================
// prep / glue kernels
// =====================================================================
// x fp32 -> fp16 hi plane only
__global__ void splitf(const float* __restrict__ in, __half* __restrict__ out, size_t n)
{
    size_t i = (size_t)blockIdx.x * blockDim.x + threadIdx.x;
    if (i < n) out[i] = __float2half_rn(in[i]);
}

// fused QKV weight transpose+split: z = which*NH + head
__global__ void tspw_qkv(const float* __restrict__ Wq, const float* __restrict__ Wk,
                         const float* __restrict__ Wv, __half* __restrict__ O)
{
    __shared__ float t[32][33];
    const int z = blockIdx.z;
    const int which = z >> 4, hh = z & 15;
    const float* Wsel = (which == 0) ? Wq : (which == 1) ? Wk : Wv;
    const float* Wb = Wsel + (size_t)hh * DM * HDIM;
    const int n0 = blockIdx.x * 32, k0 = blockIdx.y * 32;
    const int tx = threadIdx.x, ty = threadIdx.y;
    #pragma unroll
    for (int i = 0; i < 32; i += 8)
        t[ty + i][tx] = Wb[(size_t)(k0 + ty + i) * HDIM + n0 + tx];
    __syncthreads();
    const int rowOff = which * 1024 + hh * 64;
    #pragma unroll
    for (int i = 0; i < 32; i += 8) {
        __half h, l;
        split_h(t[tx][ty + i], h, l);
        size_t o = (size_t)(rowOff + n0 + ty + i) * DM + k0 + tx;
        O[o] = h;
        O[(size_t)NQKV * DM + o] = l;
    }
}

// W fp32 [K][N] -> fp16 hi plane [N][K]
__global__ void tspw(const float* __restrict__ W, __half* __restrict__ O, int K, int N)
{
    __shared__ float t[32][33];
    const int n0 = blockIdx.x * 32, k0 = blockIdx.y * 32;
    const int tx = threadIdx.x, ty = threadIdx.y;
    #pragma unroll
    for (int i = 0; i < 32; i += 8)
        t[ty + i][tx] = W[(size_t)(k0 + ty + i) * N + n0 + tx];
    __syncthreads();
    #pragma unroll
    for (int i = 0; i < 32; i += 8)
        O[(size_t)(n0 + ty + i) * K + k0 + tx] = __float2half_rn(t[tx][ty + i]);
}

// Vn[h][e][s] = fp16(Vf[h][s][e] / Z[h][s])  (hi plane only; 1/Z inline)
__global__ void rescaleV(const float* __restrict__ Vf, const float* __restrict__ Zz,
                         __half* __restrict__ Vn)
{
    __shared__ float t[32][33];
    const int h = blockIdx.z;
    const int e0 = blockIdx.x * 32, s0 = blockIdx.y * 32;
    const int tx = threadIdx.x, ty = threadIdx.y;
    const float* Vb = Vf + (size_t)h * SEQ * HDIM;
    const float* Zp = Zz + (size_t)h * SEQ;
    #pragma unroll
    for (int i = 0; i < 32; i += 8) {
        int s = s0 + ty + i;
        t[ty + i][tx] = Vb[(size_t)s * HDIM + e0 + tx] * (1.f / Zp[s]);
    }
    __syncthreads();
    __half* Ob = Vn + (size_t)h * HDIM * SEQ;
    #pragma unroll
    for (int i = 0; i < 32; i += 8) {
        size_t o = (size_t)(e0 + ty + i) * SEQ + s0 + tx;
        Ob[o] = __float2half_rn(t[tx][ty + i]);
    }
}

__global__ void zerok(float* __restrict__ p, int n)
{
    int i = blockIdx.x * blockDim.x + threadIdx.x;
    if (i < n) p[i] = 0.f;
}

// =====================================================================
extern "C" void kernel_launch(void* const* d_in, const int* in_sizes, int n_in,
                              void* d_out, int out_size)
{
    const float* x  = (const float*)d_in[0];
    const float* Wq = (const float*)d_in[1];
    const float* bq = (const float*)d_in[2];
    const float* Wk = (const float*)d_in[3];
    const float* bk = (const float*)d_in[4];
    const float* Wv = (const float*)d_in[5];
    const float* bv = (const float*)d_in[6];
    const float* Wp = (const float*)d_in[7];
    const float* bp = (const float*)d_in[8];
    const float* W1 = (const float*)d_in[9];
    const float* b1 = (const float*)d_in[10];
    const float* W2 = (const float*)d_in[11];
    const float* b2 = (const float*)d_in[12];
    float* out = (float*)d_out;

    __half *Xsp, *Wqkvt, *Wpt, *W1t, *W2t, *Qsp, *Ksp, *Vn, *Csp, *Projsp, *Hsp;
    float *Vf, *Z;
    cudaGetSymbolAddress((void**)&Xsp,    g_Xsp);
    cudaGetSymbolAddress((void**)&Wqkvt,  g_Wqkvt);
    cudaGetSymbolAddress((void**)&Wpt,    g_Wpt);
    cudaGetSymbolAddress((void**)&W1t,    g_W1t);
    cudaGetSymbolAddress((void**)&W2t,    g_W2t);
    cudaGetSymbolAddress((void**)&Qsp,    g_Qsp);
    cudaGetSymbolAddress((void**)&Ksp,    g_Ksp);
    cudaGetSymbolAddress((void**)&Vf,     g_Vf);
    cudaGetSymbolAddress((void**)&Vn,     g_Vn);
    cudaGetSymbolAddress((void**)&Z,      g_Z);
    cudaGetSymbolAddress((void**)&Csp,    g_Csp);
    cudaGetSymbolAddress((void**)&Projsp, g_Projsp);
    cudaGetSymbolAddress((void**)&Hsp,    g_Hsp);

    const int SM_12 = 2 * (1 * 10240 + 2 * 128 * 80);  // 61440 (ANP1,BNP2)
    const int SM_11 = 2 * (1 * 10240 + 1 * 128 * 80);  // 40960 (ANP1,BNP1)
    cudaFuncSetAttribute(gg<4,1,2,0,0,4>, cudaFuncAttributeMaxDynamicSharedMemorySize, SM_12);
    cudaFuncSetAttribute(gg<6,1,1,0,0,4>, cudaFuncAttributeMaxDynamicSharedMemorySize, SM_11);
    cudaFuncSetAttribute(gg<5,1,1,0,0,4>, cudaFuncAttributeMaxDynamicSharedMemorySize, SM_11);
    cudaFuncSetAttribute(gg<5,1,1,1,0,4>, cudaFuncAttributeMaxDynamicSharedMemorySize, SM_11);
    cudaFuncSetAttribute(gg<0,1,1,0,0,4>, cudaFuncAttributeMaxDynamicSharedMemorySize, SM_11);
    cudaFuncSetAttribute(fav, cudaFuncAttributeMaxDynamicSharedMemorySize, FAV_SMEM);

    dim3 tb(32, 8);
    // prep
    splitf<<<(SEQ * DM + 255) / 256, 256>>>(x, Xsp, (size_t)SEQ * DM);
    tspw_qkv<<<dim3(2, 32, NH * 3), tb>>>(Wq, Wk, Wv, Wqkvt);
    tspw<<<dim3(32, 32, 1),  tb>>>(Wp, Wpt, DM, DM);
    tspw<<<dim3(128, 32, 1), tb>>>(W1, W1t, DM, FFD);
    tspw<<<dim3(32, 128, 1), tb>>>(W2, W2t, FFD, DM);
    zerok<<<(NH * SEQ + 255) / 256, 256>>>(Z, NH * SEQ);

    // 1) fused QKV  (x hi-plane only; Q/K emitted hi-only, V fp32)
    gg<4,1,2,0,0,4><<<dim3(NQKV / 128, SEQ / 128, 1), 256, SM_12>>>(
        Xsp, Wqkvt, bq, bk, bv, nullptr, nullptr,
        DM, DM, DM, 0, 0, 0, 0, 0, (size_t)NQKV * DM, 0, 1.f);

    // 2) Z pass: Z[h,s] = sum_t exp(Khi[t].Qhi[s]/8)
    gg<6,1,1,0,0,4><<<dim3(SEQ / 128, SEQ / 128, NH), 256, SM_11>>>(
        Ksp, Qsp, nullptr, nullptr, nullptr, nullptr, Z,
        HDIM, HDIM, HDIM, SEQ,
        (size_t)SEQ * HDIM, (size_t)SEQ * HDIM, 0,
        0, 0, 0, 0.125f);

    // 3) Vn = fp16(V/Z) transposed, hi-only (1/Z inline)
    rescaleV<<<dim3(2, 64, NH), tb>>>(Vf, Z, Vn);

    // 4) fused attention (hi-only, 64-t CTAs): Csp hi plane out
    fav<<<dim3(SEQ / 64, NH), 128, FAV_SMEM>>>(Qsp, Ksp, Vn, Csp);

    // 5) proj = concat @ Wp + bp  (1 MMA; fp16 hi out)
    gg<5,1,1,0,0,4><<<dim3(DM / 128, SEQ / 128, 1), 256, SM_11>>>(
        Csp, Wpt, bp, nullptr, nullptr, Projsp, nullptr,
        DM, DM, DM, DM, 0, 0, 0,
        0, 0, 0, 1.f);

    // 6) hidden = relu(proj @ W1 + b1)  (1 MMA)
    gg<5,1,1,1,0,4><<<dim3(FFD / 128, SEQ / 128, 1), 256, SM_11>>>(
        Projsp, W1t, b1, nullptr, nullptr, Hsp, nullptr,
        DM, DM, DM, FFD, 0, 0, 0,
        0, 0, 0, 1.f);

    // 7) out = hidden @ W2 + b2  (1 MMA)
    gg<0,1,1,0,0,4><<<dim3(DM / 128, SEQ / 128, 1), 256, SM_11>>>(
        Hsp, W2t, b2, nullptr, nullptr, out, nullptr,
        FFD, FFD, FFD, DM, 0, 0, 0,
        0, 0, 0, 1.f);
}

// round 15
// speedup vs baseline: 1.0261x; 1.0261x over previous
#include <cuda_runtime.h>
#include <cuda_fp16.h>
#include <cstdint>

#define SEQ  2048
#define DM   1024
#define NH   16
#define HDIM 64
#define FFD  4096
#define NQKV 3072

// ---------------- scratch (no allocations allowed) ----------------
__device__ __half g_Xsp[(size_t)SEQ * DM];      // hi plane only
__device__ __half g_Wqkvt[2u * NQKV * DM];
__device__ __half g_Wpt[(size_t)DM * DM];       // hi plane only
__device__ __half g_W1t[(size_t)FFD * DM];      // hi plane only
__device__ __half g_W2t[(size_t)DM * FFD];      // hi plane only
__device__ __half g_Qsp[NH * SEQ * HDIM];       // hi plane only
__device__ __half g_Ksp[NH * SEQ * HDIM];       // hi plane only
__device__ float  g_Vf[NH * SEQ * HDIM];
__device__ __half g_Vn[NH * HDIM * SEQ];        // hi plane only
__device__ float  g_Z[NH * SEQ];
__device__ __half g_Csp[(size_t)SEQ * DM];      // hi plane only
__device__ __half g_Projsp[(size_t)SEQ * DM];   // hi plane only
__device__ __half g_Hsp[(size_t)SEQ * FFD];     // hi plane only

// ---------------- helpers ----------------
__device__ __forceinline__ void split_h(float a, __half& h, __half& l) {
    h = __float2half_rn(a);
    l = __float2half_rn(a - __half2float(h));
}
__device__ __forceinline__ uint32_t pkh(__half a, __half b) {
    __half2 t(a, b);
    return *reinterpret_cast<uint32_t*>(&t);
}
__device__ __forceinline__ void ldsm4(uint32_t& r0, uint32_t& r1, uint32_t& r2, uint32_t& r3, uint32_t a) {
    asm volatile("ldmatrix.sync.aligned.m8n8.x4.shared.b16 {%0,%1,%2,%3}, [%4];"
                 : "=r"(r0), "=r"(r1), "=r"(r2), "=r"(r3) : "r"(a));
}
__device__ __forceinline__ void mma_h(float c[4], const uint32_t a[4], const uint32_t b[2]) {
    asm volatile(
        "mma.sync.aligned.m16n8k16.row.col.f32.f16.f16.f32 "
        "{%0,%1,%2,%3}, {%4,%5,%6,%7}, {%8,%9}, {%0,%1,%2,%3};"
        : "+f"(c[0]), "+f"(c[1]), "+f"(c[2]), "+f"(c[3])
        : "r"(a[0]), "r"(a[1]), "r"(a[2]), "r"(a[3]), "r"(b[0]), "r"(b[1]));
}
__device__ __forceinline__ void cp16(uint32_t dst, const void* src) {
    asm volatile("cp.async.cg.shared.global [%0], [%1], 16;" :: "r"(dst), "l"(src));
}
__device__ __forceinline__ void cp_commit() {
    asm volatile("cp.async.commit_group;" ::: "memory");
}
template <int N>
__device__ __forceinline__ void cp_wait() {
    asm volatile("cp.async.wait_group %0;" :: "n"(N) : "memory");
}

// =====================================================================
// fp16 split mma.sync GEMM.  CTA 128(M) x 32*NW2(N), BK=32.
// ANP/BNP: number of A/B fp16 planes.
// EPI: 0 fp32+bias, 4 QKV scatter (Q/K hi-only, V fp32),
//      5 fp16 hi-only out+bias(+relu), 6 exp -> col-Z atomics (no store).
// =====================================================================
template <int EPI, int ANP, int BNP, int RELU, int SKBITS, int NW2>
__global__ void __launch_bounds__(NW2 * 64, (NW2 == 2) ? 3 : 2)
gg(const __half* __restrict__ A, const __half* __restrict__ B,
   const float* __restrict__ bias, const float* __restrict__ bias2,
   const float* __restrict__ bias3, void* __restrict__ Cv,
   float* __restrict__ Zb,
   int K, int lda, int ldb, int ldc,
   size_t aZ, size_t bZ, size_t cZ, size_t pA, size_t pB, size_t pC,
   float scale)
{
    constexpr int T     = NW2 * 64;
    constexpr int BNT   = 32 * NW2;
    constexpr int ASEG_ = 10240;
    constexpr int BSEG_ = BNT * 80;
    constexpr int STG   = ANP * ASEG_ + BNP * BSEG_;
    constexpr int CA    = 512 / T;

    extern __shared__ __align__(16) unsigned char sm[];
    const uint32_t smb = (uint32_t)__cvta_generic_to_shared(sm);

    const int tid = threadIdx.x;
    const int warp = tid >> 5, lane = tid & 31;
    const int g = lane >> 2, tg = lane & 3;
    const int b3 = (lane >> 3) & 1, b4 = (lane >> 4) & 1;
    const int m0 = (warp & 1) * 64, n0 = (warp >> 1) * 32;

    const int z = blockIdx.z;
    const int zhead = z >> SKBITS;
    const int bm = blockIdx.y * 128;
    const int bn = blockIdx.x * BNT;

    const __half* Ag = A + zhead * aZ;
    const __half* Bg = B + zhead * bZ;

    uint32_t aOff[4], bOff[2];
    #pragma unroll
    for (int tm = 0; tm < 4; tm++)
        aOff[tm] = ((m0 + tm * 16 + (lane & 7) + b3 * 8) * 40 + b4 * 8) * 2;
    #pragma unroll
    for (int q = 0; q < 2; q++)
        bOff[q] = ((n0 + q * 16 + (lane & 7) + b4 * 8) * 40 + b3 * 8) * 2;

    auto ldgsts = [&](int st, int slab) {
        const int k0 = slab << 5;
        #pragma unroll
        for (int p = 0; p < ANP; p++)
            #pragma unroll
            for (int j = 0; j < CA; j++) {
                int idx = tid + j * T;
                int row = idx >> 2, kc = idx & 3;
                cp16(smb + st * STG + p * ASEG_ + row * 80 + kc * 16,
                     Ag + p * pA + (size_t)(bm + row) * lda + k0 + kc * 8);
            }
        #pragma unroll
        for (int p = 0; p < BNP; p++)
            #pragma unroll
            for (int j = 0; j < 2; j++) {
                int idx = tid + j * T;
                int row = idx >> 2, kc = idx & 3;
                cp16(smb + st * STG + ANP * ASEG_ + p * BSEG_ + row * 80 + kc * 16,
                     Bg + p * pB + (size_t)(bn + row) * ldb + k0 + kc * 8);
            }
        cp_commit();
    };

    float acc[4][4][4];
    #pragma unroll
    for (int tm = 0; tm < 4; tm++)
        #pragma unroll
        for (int tn = 0; tn < 4; tn++)
            #pragma unroll
            for (int r = 0; r < 4; r++) acc[tm][tn][r] = 0.f;

    const int ns = K >> 5;
    ldgsts(0, 0);
    ldgsts(1, 1);
    cp_wait<1>();
    __syncthreads();

    for (int i = 0; i < ns; i++) {
        const int buf = i & 1;
        const uint32_t aB = smb + buf * STG;
        const uint32_t bB = smb + buf * STG + ANP * ASEG_;
        #pragma unroll
        for (int ks = 0; ks < 2; ks++) {
            uint32_t af[4][ANP][4], bf[BNP][4][2];
            #pragma unroll
            for (int tm = 0; tm < 4; tm++)
                #pragma unroll
                for (int p = 0; p < ANP; p++)
                    ldsm4(af[tm][p][0], af[tm][p][1], af[tm][p][2], af[tm][p][3],
                          aB + p * ASEG_ + aOff[tm] + ks * 32);
            #pragma unroll
            for (int p = 0; p < BNP; p++)
                #pragma unroll
                for (int q = 0; q < 2; q++) {
                    uint32_t r0, r1, r2, r3;
                    ldsm4(r0, r1, r2, r3, bB + p * BSEG_ + bOff[q] + ks * 32);
                    bf[p][q * 2 + 0][0] = r0; bf[p][q * 2 + 0][1] = r1;
                    bf[p][q * 2 + 1][0] = r2; bf[p][q * 2 + 1][1] = r3;
                }
            #pragma unroll
            for (int tm = 0; tm < 4; tm++)
                #pragma unroll
                for (int tn = 0; tn < 4; tn++) {
                    mma_h(acc[tm][tn], af[tm][0], bf[0][tn]);
                    if (BNP == 2) mma_h(acc[tm][tn], af[tm][0], bf[1][tn]);
                    if (ANP == 2) mma_h(acc[tm][tn], af[tm][1], bf[0][tn]);
                }
        }
        __syncthreads();
        if (i + 2 < ns) ldgsts(buf, i + 2);
        if (i + 1 < ns) {
            if (i + 2 < ns) cp_wait<1>(); else cp_wait<0>();
            __syncthreads();
        }
    }

    // ------------------ epilogues ------------------
    if (EPI == 6) {
        float cs[4][2];
        #pragma unroll
        for (int tn = 0; tn < 4; tn++) { cs[tn][0] = 0.f; cs[tn][1] = 0.f; }
        #pragma unroll
        for (int tm = 0; tm < 4; tm++)
            #pragma unroll
            for (int half = 0; half < 2; half++)
                #pragma unroll
                for (int tn = 0; tn < 4; tn++) {
                    cs[tn][0] += __expf(acc[tm][tn][half * 2 + 0] * scale);
                    cs[tn][1] += __expf(acc[tm][tn][half * 2 + 1] * scale);
                }
        float* Zp = Zb + (size_t)zhead * SEQ;
        #pragma unroll
        for (int tn = 0; tn < 4; tn++)
            #pragma unroll
            for (int j = 0; j < 2; j++) {
                float v = cs[tn][j];
                v += __shfl_xor_sync(0xffffffffu, v, 4);
                v += __shfl_xor_sync(0xffffffffu, v, 8);
                v += __shfl_xor_sync(0xffffffffu, v, 16);
                if (lane < 4) atomicAdd(Zp + bn + n0 + tn * 8 + 2 * tg + j, v);
            }
    } else if (EPI == 4) {
        #pragma unroll
        for (int tn = 0; tn < 4; tn++) {
            const int eg  = bn + n0 + tn * 8 + 2 * tg;
            const int seg = eg >> 10;
            const int hh  = (eg >> 6) & 15;
            const int e   = eg & 63;
            const float* bsel = (seg == 0) ? bias : (seg == 1) ? bias2 : bias3;
            float2 bb = *(const float2*)(bsel + hh * 64 + e);
            #pragma unroll
            for (int tm = 0; tm < 4; tm++)
                #pragma unroll
                for (int half = 0; half < 2; half++) {
                    const int row = bm + m0 + tm * 16 + g + half * 8;
                    float vx = acc[tm][tn][half * 2 + 0] + bb.x;
                    float vy = acc[tm][tn][half * 2 + 1] + bb.y;
                    if (seg == 2) {
                        *(float2*)(g_Vf + ((size_t)hh * SEQ + row) * HDIM + e) =
                            make_float2(vx, vy);
                    } else {
                        __half* O = (seg == 0) ? g_Qsp : g_Ksp;
                        size_t base = (size_t)hh * SEQ * HDIM + (size_t)row * HDIM + e;
                        *(uint32_t*)(O + base) =
                            pkh(__float2half_rn(vx), __float2half_rn(vy));
                    }
                }
        }
    } else if (EPI == 5) {
        __half* Ch = (__half*)Cv + zhead * cZ;
        #pragma unroll
        for (int tn = 0; tn < 4; tn++) {
            const int col = bn + n0 + tn * 8 + 2 * tg;
            float2 bb = *(const float2*)(bias + col);
            #pragma unroll
            for (int tm = 0; tm < 4; tm++)
                #pragma unroll
                for (int half = 0; half < 2; half++) {
                    const int row = bm + m0 + tm * 16 + g + half * 8;
                    float vx = acc[tm][tn][half * 2 + 0] + bb.x;
                    float vy = acc[tm][tn][half * 2 + 1] + bb.y;
                    if (RELU) { vx = fmaxf(vx, 0.f); vy = fmaxf(vy, 0.f); }
                    *(uint32_t*)(Ch + (size_t)row * ldc + col) =
                        pkh(__float2half_rn(vx), __float2half_rn(vy));
                }
        }
    } else {
        float* C = (float*)Cv + zhead * cZ;
        #pragma unroll
        for (int tn = 0; tn < 4; tn++) {
            const int col = bn + n0 + tn * 8 + 2 * tg;
            float2 bb = *(const float2*)(bias + col);
            #pragma unroll
            for (int tm = 0; tm < 4; tm++)
                #pragma unroll
                for (int half = 0; half < 2; half++) {
                    const int row = bm + m0 + tm * 16 + g + half * 8;
                    *(float2*)(C + (size_t)row * ldc + col) =
                        make_float2(acc[tm][tn][half * 2 + 0] + bb.x,
                                    acc[tm][tn][half * 2 + 1] + bb.y);
                }
        }
    }
}

// =====================================================================
// Fused attention (hi-only): O[t, h*64+e] = sum_s exp(Khi[t].Qhi[s]/8) Vhi[e,s]
// Per CTA: 128 t-rows (4 warps x 32 rows), one head; s in 32-slabs,
// double-buffered.  smem: K 2x10240 | stage{0,1} 10240: Q 5120 | V 5120.
// Output: Csp hi plane only.
// =====================================================================
#define FAV_SMEM 40960

__global__ void __launch_bounds__(128, 3)
fav(const __half* __restrict__ Qsp, const __half* __restrict__ Ksp,
    const __half* __restrict__ Vn, __half* __restrict__ Csp)
{
    extern __shared__ __align__(16) unsigned char sm[];
    const uint32_t smb = (uint32_t)__cvta_generic_to_shared(sm);

    const int tid = threadIdx.x;
    const int warp = tid >> 5, lane = tid & 31;
    const int g = lane >> 2, tg = lane & 3;
    const int b3 = (lane >> 3) & 1, b4 = (lane >> 4) & 1;
    const int m0 = warp * 32;

    const int bt = blockIdx.x * 128;
    const int h  = blockIdx.y;

    const __half* Kh = Ksp + (size_t)h * SEQ * HDIM;
    const __half* Qh = Qsp + (size_t)h * SEQ * HDIM;
    const __half* Vh = Vn + (size_t)h * HDIM * SEQ;

    uint32_t aOffK[2], bOffQ[2], bOffV[4];
    #pragma unroll
    for (int tm = 0; tm < 2; tm++)
        aOffK[tm] = ((m0 + tm * 16 + (lane & 7) + b3 * 8) * 40 + b4 * 8) * 2;
    #pragma unroll
    for (int q = 0; q < 2; q++)
        bOffQ[q] = ((q * 16 + (lane & 7) + b4 * 8) * 40 + b3 * 8) * 2;
    #pragma unroll
    for (int q = 0; q < 4; q++)
        bOffV[q] = ((q * 16 + (lane & 7) + b4 * 8) * 40 + b3 * 8) * 2;

    // ---- K tile (once): 2 kslabs x [128 rows x 80B] ----
    #pragma unroll
    for (int j = 0; j < 8; j++) {
        int idx = tid + j * 128;
        int slab = idx >> 9;
        int r = (idx & 511) >> 2;
        int c = idx & 3;
        cp16(smb + slab * 10240 + r * 80 + c * 16,
             Kh + (size_t)(bt + r) * HDIM + slab * 32 + c * 8);
    }
    cp_commit();

    auto ldStage = [&](int st, int s0) {
        const uint32_t base = smb + 20480 + st * 10240;
        #pragma unroll
        for (int j = 0; j < 2; j++) {            // Q: 2 kslabs x [32 x 80B]
            int idx = tid + j * 128;
            int ksl = idx >> 7;
            int r = (idx & 127) >> 2;
            int c = idx & 3;
            cp16(base + ksl * 2560 + r * 80 + c * 16,
                 Qh + (size_t)(s0 + r) * HDIM + ksl * 32 + c * 8);
        }
        #pragma unroll
        for (int j = 0; j < 2; j++) {            // V: [64 e x 80B]
            int idx = tid + j * 128;
            int e = idx >> 2;
            int c = idx & 3;
            cp16(base + 5120 + e * 80 + c * 16,
                 Vh + (size_t)e * SEQ + s0 + c * 8);
        }
        cp_commit();
    };

    float O[2][8][4];
    #pragma unroll
    for (int tm = 0; tm < 2; tm++)
        #pragma unroll
        for (int tn = 0; tn < 8; tn++)
            #pragma unroll
            for (int r = 0; r < 4; r++) O[tm][tn][r] = 0.f;

    const int ns = SEQ / 32;
    ldStage(0, 0);
    ldStage(1, 32);
    cp_wait<1>();
    __syncthreads();

    for (int i = 0; i < ns; i++) {
        const int buf = i & 1;
        const uint32_t stg = smb + 20480 + buf * 10240;

        // ---- MMA1: S[128 x 32] = Khi . Qhi ----
        float S[2][4][4];
        #pragma unroll
        for (int tm = 0; tm < 2; tm++)
            #pragma unroll
            for (int tn = 0; tn < 4; tn++)
                #pragma unroll
                for (int r = 0; r < 4; r++) S[tm][tn][r] = 0.f;

        #pragma unroll
        for (int kk = 0; kk < 4; kk++) {
            const int j = kk >> 1, ksl = kk & 1;
            uint32_t aK[2][4], bq[4][2];
            #pragma unroll
            for (int tm = 0; tm < 2; tm++)
                ldsm4(aK[tm][0], aK[tm][1], aK[tm][2], aK[tm][3],
                      smb + j * 10240 + aOffK[tm] + ksl * 32);
            #pragma unroll
            for (int q = 0; q < 2; q++) {
                uint32_t r0, r1, r2, r3;
                ldsm4(r0, r1, r2, r3, stg + j * 2560 + bOffQ[q] + ksl * 32);
                bq[q * 2 + 0][0] = r0; bq[q * 2 + 0][1] = r1;
                bq[q * 2 + 1][0] = r2; bq[q * 2 + 1][1] = r3;
            }
            #pragma unroll
            for (int tm = 0; tm < 2; tm++)
                #pragma unroll
                for (int tn = 0; tn < 4; tn++)
                    mma_h(S[tm][tn], aK[tm], bq[tn]);
        }

        // ---- exp + MMA2: O += P . Vhi ----
        #pragma unroll
        for (int kk2 = 0; kk2 < 2; kk2++) {
            uint32_t pa[2][4];
            #pragma unroll
            for (int tm = 0; tm < 2; tm++) {
                const int nt0 = 2 * kk2, nt1 = nt0 + 1;
                pa[tm][0] = pkh(__float2half_rn(__expf(S[tm][nt0][0] * 0.125f)),
                                __float2half_rn(__expf(S[tm][nt0][1] * 0.125f)));
                pa[tm][1] = pkh(__float2half_rn(__expf(S[tm][nt0][2] * 0.125f)),
                                __float2half_rn(__expf(S[tm][nt0][3] * 0.125f)));
                pa[tm][2] = pkh(__float2half_rn(__expf(S[tm][nt1][0] * 0.125f)),
                                __float2half_rn(__expf(S[tm][nt1][1] * 0.125f)));
                pa[tm][3] = pkh(__float2half_rn(__expf(S[tm][nt1][2] * 0.125f)),
                                __float2half_rn(__expf(S[tm][nt1][3] * 0.125f)));
            }
            #pragma unroll
            for (int q = 0; q < 4; q++) {
                uint32_t r0, r1, r2, r3;
                ldsm4(r0, r1, r2, r3, stg + 5120 + bOffV[q] + kk2 * 32);
                uint32_t bv0[2] = {r0, r1};
                uint32_t bv1[2] = {r2, r3};
                #pragma unroll
                for (int tm = 0; tm < 2; tm++) {
                    mma_h(O[tm][q * 2 + 0], pa[tm], bv0);
                    mma_h(O[tm][q * 2 + 1], pa[tm], bv1);
                }
            }
        }

        __syncthreads();
        if (i + 2 < ns) ldStage(buf, (i + 2) * 32);
        if (i + 1 < ns) {
            if (i + 2 < ns) cp_wait<1>(); else cp_wait<0>();
            __syncthreads();
        }
    }

    // ---- epilogue: Csp hi plane only, col = h*64 + e ----
    #pragma unroll
    for (int tm = 0; tm < 2; tm++)
        #pragma unroll
        for (int tn = 0; tn < 8; tn++) {
            const int col = h * 64 + tn * 8 + 2 * tg;
            #pragma unroll
            for (int half = 0; half < 2; half++) {
                const int row = bt + m0 + tm * 16 + g + half * 8;
                *(uint32_t*)(Csp + (size_t)row * DM + col) =
                    pkh(__float2half_rn(O[tm][tn][half * 2 + 0]),
                        __float2half_rn(O[tm][tn][half * 2 + 1]));
            }
        }
}

// =====================================================================
// prep / glue kernels
// =====================================================================
// x fp32 -> fp16 hi plane only
__global__ void splitf(const float* __restrict__ in, __half* __restrict__ out, size_t n)
{
    size_t i = (size_t)blockIdx.x * blockDim.x + threadIdx.x;
    if (i < n) out[i] = __float2half_rn(in[i]);
}

// fused QKV weight transpose+split: z = which*NH + head
__global__ void tspw_qkv(const float* __restrict__ Wq, const float* __restrict__ Wk,
                         const float* __restrict__ Wv, __half* __restrict__ O)
{
    __shared__ float t[32][33];
    const int z = blockIdx.z;
    const int which = z >> 4, hh = z & 15;
    const float* Wsel = (which == 0) ? Wq : (which == 1) ? Wk : Wv;
    const float* Wb = Wsel + (size_t)hh * DM * HDIM;
    const int n0 = blockIdx.x * 32, k0 = blockIdx.y * 32;
    const int tx = threadIdx.x, ty = threadIdx.y;
    #pragma unroll
    for (int i = 0; i < 32; i += 8)
        t[ty + i][tx] = Wb[(size_t)(k0 + ty + i) * HDIM + n0 + tx];
    __syncthreads();
    const int rowOff = which * 1024 + hh * 64;
    #pragma unroll
    for (int i = 0; i < 32; i += 8) {
        __half h, l;
        split_h(t[tx][ty + i], h, l);
        size_t o = (size_t)(rowOff + n0 + ty + i) * DM + k0 + tx;
        O[o] = h;
        O[(size_t)NQKV * DM + o] = l;
    }
}

// W fp32 [K][N] -> fp16 hi plane [N][K]
__global__ void tspw(const float* __restrict__ W, __half* __restrict__ O, int K, int N)
{
    __shared__ float t[32][33];
    const int n0 = blockIdx.x * 32, k0 = blockIdx.y * 32;
    const int tx = threadIdx.x, ty = threadIdx.y;
    #pragma unroll
    for (int i = 0; i < 32; i += 8)
        t[ty + i][tx] = W[(size_t)(k0 + ty + i) * N + n0 + tx];
    __syncthreads();
    #pragma unroll
    for (int i = 0; i < 32; i += 8)
        O[(size_t)(n0 + ty + i) * K + k0 + tx] = __float2half_rn(t[tx][ty + i]);
}

// Vn[h][e][s] = fp16(Vf[h][s][e] / Z[h][s])  (hi plane only; 1/Z inline)
__global__ void rescaleV(const float* __restrict__ Vf, const float* __restrict__ Zz,
                         __half* __restrict__ Vn)
{
    __shared__ float t[32][33];
    const int h = blockIdx.z;
    const int e0 = blockIdx.x * 32, s0 = blockIdx.y * 32;
    const int tx = threadIdx.x, ty = threadIdx.y;
    const float* Vb = Vf + (size_t)h * SEQ * HDIM;
    const float* Zp = Zz + (size_t)h * SEQ;
    #pragma unroll
    for (int i = 0; i < 32; i += 8) {
        int s = s0 + ty + i;
        t[ty + i][tx] = Vb[(size_t)s * HDIM + e0 + tx] * (1.f / Zp[s]);
    }
    __syncthreads();
    __half* Ob = Vn + (size_t)h * HDIM * SEQ;
    #pragma unroll
    for (int i = 0; i < 32; i += 8) {
        size_t o = (size_t)(e0 + ty + i) * SEQ + s0 + tx;
        Ob[o] = __float2half_rn(t[tx][ty + i]);
    }
}

__global__ void zerok(float* __restrict__ p, int n)
{
    int i = blockIdx.x * blockDim.x + threadIdx.x;
    if (i < n) p[i] = 0.f;
}

// =====================================================================
extern "C" void kernel_launch(void* const* d_in, const int* in_sizes, int n_in,
                              void* d_out, int out_size)
{
    const float* x  = (const float*)d_in[0];
    const float* Wq = (const float*)d_in[1];
    const float* bq = (const float*)d_in[2];
    const float* Wk = (const float*)d_in[3];
    const float* bk = (const float*)d_in[4];
    const float* Wv = (const float*)d_in[5];
    const float* bv = (const float*)d_in[6];
    const float* Wp = (const float*)d_in[7];
    const float* bp = (const float*)d_in[8];
    const float* W1 = (const float*)d_in[9];
    const float* b1 = (const float*)d_in[10];
    const float* W2 = (const float*)d_in[11];
    const float* b2 = (const float*)d_in[12];
    float* out = (float*)d_out;

    __half *Xsp, *Wqkvt, *Wpt, *W1t, *W2t, *Qsp, *Ksp, *Vn, *Csp, *Projsp, *Hsp;
    float *Vf, *Z;
    cudaGetSymbolAddress((void**)&Xsp,    g_Xsp);
    cudaGetSymbolAddress((void**)&Wqkvt,  g_Wqkvt);
    cudaGetSymbolAddress((void**)&Wpt,    g_Wpt);
    cudaGetSymbolAddress((void**)&W1t,    g_W1t);
    cudaGetSymbolAddress((void**)&W2t,    g_W2t);
    cudaGetSymbolAddress((void**)&Qsp,    g_Qsp);
    cudaGetSymbolAddress((void**)&Ksp,    g_Ksp);
    cudaGetSymbolAddress((void**)&Vf,     g_Vf);
    cudaGetSymbolAddress((void**)&Vn,     g_Vn);
    cudaGetSymbolAddress((void**)&Z,      g_Z);
    cudaGetSymbolAddress((void**)&Csp,    g_Csp);
    cudaGetSymbolAddress((void**)&Projsp, g_Projsp);
    cudaGetSymbolAddress((void**)&Hsp,    g_Hsp);

    const int SM_12 = 2 * (1 * 10240 + 2 * 128 * 80);  // 61440 (ANP1,BNP2)
    const int SM_11 = 2 * (1 * 10240 + 1 * 128 * 80);  // 40960 (ANP1,BNP1)
    cudaFuncSetAttribute(gg<4,1,2,0,0,4>, cudaFuncAttributeMaxDynamicSharedMemorySize, SM_12);
    cudaFuncSetAttribute(gg<6,1,1,0,0,4>, cudaFuncAttributeMaxDynamicSharedMemorySize, SM_11);
    cudaFuncSetAttribute(gg<5,1,1,0,0,4>, cudaFuncAttributeMaxDynamicSharedMemorySize, SM_11);
    cudaFuncSetAttribute(gg<5,1,1,1,0,4>, cudaFuncAttributeMaxDynamicSharedMemorySize, SM_11);
    cudaFuncSetAttribute(gg<0,1,1,0,0,4>, cudaFuncAttributeMaxDynamicSharedMemorySize, SM_11);
    cudaFuncSetAttribute(fav, cudaFuncAttributeMaxDynamicSharedMemorySize, FAV_SMEM);

    dim3 tb(32, 8);
    // prep
    splitf<<<(SEQ * DM + 255) / 256, 256>>>(x, Xsp, (size_t)SEQ * DM);
    tspw_qkv<<<dim3(2, 32, NH * 3), tb>>>(Wq, Wk, Wv, Wqkvt);
    tspw<<<dim3(32, 32, 1),  tb>>>(Wp, Wpt, DM, DM);
    tspw<<<dim3(128, 32, 1), tb>>>(W1, W1t, DM, FFD);
    tspw<<<dim3(32, 128, 1), tb>>>(W2, W2t, FFD, DM);
    zerok<<<(NH * SEQ + 255) / 256, 256>>>(Z, NH * SEQ);

    // 1) fused QKV  (x hi-plane only; Q/K emitted hi-only, V fp32)
    gg<4,1,2,0,0,4><<<dim3(NQKV / 128, SEQ / 128, 1), 256, SM_12>>>(
        Xsp, Wqkvt, bq, bk, bv, nullptr, nullptr,
        DM, DM, DM, 0, 0, 0, 0, 0, (size_t)NQKV * DM, 0, 1.f);

    // 2) Z pass: Z[h,s] = sum_t exp(Khi[t].Qhi[s]/8)
    gg<6,1,1,0,0,4><<<dim3(SEQ / 128, SEQ / 128, NH), 256, SM_11>>>(
        Ksp, Qsp, nullptr, nullptr, nullptr, nullptr, Z,
        HDIM, HDIM, HDIM, SEQ,
        (size_t)SEQ * HDIM, (size_t)SEQ * HDIM, 0,
        0, 0, 0, 0.125f);

    // 3) Vn = fp16(V/Z) transposed, hi-only (1/Z inline)
    rescaleV<<<dim3(2, 64, NH), tb>>>(Vf, Z, Vn);

    // 4) fused attention (hi-only, 128-t CTAs): Csp hi plane out
    fav<<<dim3(SEQ / 128, NH), 128, FAV_SMEM>>>(Qsp, Ksp, Vn, Csp);

    // 5) proj = concat @ Wp + bp  (1 MMA; fp16 hi out)
    gg<5,1,1,0,0,4><<<dim3(DM / 128, SEQ / 128, 1), 256, SM_11>>>(
        Csp, Wpt, bp, nullptr, nullptr, Projsp, nullptr,
        DM, DM, DM, DM, 0, 0, 0,
        0, 0, 0, 1.f);

    // 6) hidden = relu(proj @ W1 + b1)  (1 MMA)
    gg<5,1,1,1,0,4><<<dim3(FFD / 128, SEQ / 128, 1), 256, SM_11>>>(
        Projsp, W1t, b1, nullptr, nullptr, Hsp, nullptr,
        DM, DM, DM, FFD, 0, 0, 0,
        0, 0, 0, 1.f);

    // 7) out = hidden @ W2 + b2  (1 MMA)
    gg<0,1,1,0,0,4><<<dim3(DM / 128, SEQ / 128, 1), 256, SM_11>>>(
        Hsp, W2t, b2, nullptr, nullptr, out, nullptr,
        FFD, FFD, FFD, DM, 0, 0, 0,
        0, 0, 0, 1.f);
}

// round 16
// speedup vs baseline: 1.1220x; 1.0935x over previous
#include <cuda_runtime.h>
#include <cuda_fp16.h>
#include <cstdint>

#define SEQ  2048
#define DM   1024
#define NH   16
#define HDIM 64
#define FFD  4096
#define NQKV 3072

// ---------------- scratch (no allocations allowed) ----------------
__device__ __half g_Xsp[(size_t)SEQ * DM];      // hi plane only
__device__ __half g_Wqkvt[(size_t)NQKV * DM];   // hi plane only
__device__ __half g_Wpt[(size_t)DM * DM];       // hi plane only
__device__ __half g_W1t[(size_t)FFD * DM];      // hi plane only
__device__ __half g_W2t[(size_t)DM * FFD];      // hi plane only
__device__ __half g_Qsp[NH * SEQ * HDIM];       // hi plane only
__device__ __half g_Ksp[NH * SEQ * HDIM];       // hi plane only
__device__ float  g_Vf[NH * SEQ * HDIM];
__device__ __half g_Vn[NH * HDIM * SEQ];        // hi plane only
__device__ float  g_Z[NH * SEQ];
__device__ __half g_Csp[(size_t)SEQ * DM];      // hi plane only
__device__ __half g_Projsp[(size_t)SEQ * DM];   // hi plane only
__device__ __half g_Hsp[(size_t)SEQ * FFD];     // hi plane only

// ---------------- helpers ----------------
__device__ __forceinline__ uint32_t pkh(__half a, __half b) {
    __half2 t(a, b);
    return *reinterpret_cast<uint32_t*>(&t);
}
__device__ __forceinline__ void ldsm4(uint32_t& r0, uint32_t& r1, uint32_t& r2, uint32_t& r3, uint32_t a) {
    asm volatile("ldmatrix.sync.aligned.m8n8.x4.shared.b16 {%0,%1,%2,%3}, [%4];"
                 : "=r"(r0), "=r"(r1), "=r"(r2), "=r"(r3) : "r"(a));
}
__device__ __forceinline__ void mma_h(float c[4], const uint32_t a[4], const uint32_t b[2]) {
    asm volatile(
        "mma.sync.aligned.m16n8k16.row.col.f32.f16.f16.f32 "
        "{%0,%1,%2,%3}, {%4,%5,%6,%7}, {%8,%9}, {%0,%1,%2,%3};"
        : "+f"(c[0]), "+f"(c[1]), "+f"(c[2]), "+f"(c[3])
        : "r"(a[0]), "r"(a[1]), "r"(a[2]), "r"(a[3]), "r"(b[0]), "r"(b[1]));
}
__device__ __forceinline__ void cp16(uint32_t dst, const void* src) {
    asm volatile("cp.async.cg.shared.global [%0], [%1], 16;" :: "r"(dst), "l"(src));
}
__device__ __forceinline__ void cp_commit() {
    asm volatile("cp.async.commit_group;" ::: "memory");
}
template <int N>
__device__ __forceinline__ void cp_wait() {
    asm volatile("cp.async.wait_group %0;" :: "n"(N) : "memory");
}

// =====================================================================
// fp16 mma.sync GEMM.  CTA 128(M) x 32*NW2(N), BK=32.
// ANP/BNP: number of A/B fp16 planes.
// EPI: 0 fp32+bias, 4 QKV scatter (Q/K hi-only, V fp32),
//      5 fp16 hi-only out+bias(+relu), 6 exp -> col-Z atomics (no store).
// =====================================================================
template <int EPI, int ANP, int BNP, int RELU, int SKBITS, int NW2>
__global__ void __launch_bounds__(NW2 * 64, (NW2 == 2) ? 3 : 2)
gg(const __half* __restrict__ A, const __half* __restrict__ B,
   const float* __restrict__ bias, const float* __restrict__ bias2,
   const float* __restrict__ bias3, void* __restrict__ Cv,
   float* __restrict__ Zb,
   int K, int lda, int ldb, int ldc,
   size_t aZ, size_t bZ, size_t cZ, size_t pA, size_t pB, size_t pC,
   float scale)
{
    constexpr int T     = NW2 * 64;
    constexpr int BNT   = 32 * NW2;
    constexpr int ASEG_ = 10240;
    constexpr int BSEG_ = BNT * 80;
    constexpr int STG   = ANP * ASEG_ + BNP * BSEG_;
    constexpr int CA    = 512 / T;

    extern __shared__ __align__(16) unsigned char sm[];
    const uint32_t smb = (uint32_t)__cvta_generic_to_shared(sm);

    const int tid = threadIdx.x;
    const int warp = tid >> 5, lane = tid & 31;
    const int g = lane >> 2, tg = lane & 3;
    const int b3 = (lane >> 3) & 1, b4 = (lane >> 4) & 1;
    const int m0 = (warp & 1) * 64, n0 = (warp >> 1) * 32;

    const int z = blockIdx.z;
    const int zhead = z >> SKBITS;
    const int bm = blockIdx.y * 128;
    const int bn = blockIdx.x * BNT;

    const __half* Ag = A + zhead * aZ;
    const __half* Bg = B + zhead * bZ;

    uint32_t aOff[4], bOff[2];
    #pragma unroll
    for (int tm = 0; tm < 4; tm++)
        aOff[tm] = ((m0 + tm * 16 + (lane & 7) + b3 * 8) * 40 + b4 * 8) * 2;
    #pragma unroll
    for (int q = 0; q < 2; q++)
        bOff[q] = ((n0 + q * 16 + (lane & 7) + b4 * 8) * 40 + b3 * 8) * 2;

    auto ldgsts = [&](int st, int slab) {
        const int k0 = slab << 5;
        #pragma unroll
        for (int p = 0; p < ANP; p++)
            #pragma unroll
            for (int j = 0; j < CA; j++) {
                int idx = tid + j * T;
                int row = idx >> 2, kc = idx & 3;
                cp16(smb + st * STG + p * ASEG_ + row * 80 + kc * 16,
                     Ag + p * pA + (size_t)(bm + row) * lda + k0 + kc * 8);
            }
        #pragma unroll
        for (int p = 0; p < BNP; p++)
            #pragma unroll
            for (int j = 0; j < 2; j++) {
                int idx = tid + j * T;
                int row = idx >> 2, kc = idx & 3;
                cp16(smb + st * STG + ANP * ASEG_ + p * BSEG_ + row * 80 + kc * 16,
                     Bg + p * pB + (size_t)(bn + row) * ldb + k0 + kc * 8);
            }
        cp_commit();
    };

    float acc[4][4][4];
    #pragma unroll
    for (int tm = 0; tm < 4; tm++)
        #pragma unroll
        for (int tn = 0; tn < 4; tn++)
            #pragma unroll
            for (int r = 0; r < 4; r++) acc[tm][tn][r] = 0.f;

    const int ns = K >> 5;
    ldgsts(0, 0);
    ldgsts(1, 1);
    cp_wait<1>();
    __syncthreads();

    for (int i = 0; i < ns; i++) {
        const int buf = i & 1;
        const uint32_t aB = smb + buf * STG;
        const uint32_t bB = smb + buf * STG + ANP * ASEG_;
        #pragma unroll
        for (int ks = 0; ks < 2; ks++) {
            uint32_t af[4][ANP][4], bf[BNP][4][2];
            #pragma unroll
            for (int tm = 0; tm < 4; tm++)
                #pragma unroll
                for (int p = 0; p < ANP; p++)
                    ldsm4(af[tm][p][0], af[tm][p][1], af[tm][p][2], af[tm][p][3],
                          aB + p * ASEG_ + aOff[tm] + ks * 32);
            #pragma unroll
            for (int p = 0; p < BNP; p++)
                #pragma unroll
                for (int q = 0; q < 2; q++) {
                    uint32_t r0, r1, r2, r3;
                    ldsm4(r0, r1, r2, r3, bB + p * BSEG_ + bOff[q] + ks * 32);
                    bf[p][q * 2 + 0][0] = r0; bf[p][q * 2 + 0][1] = r1;
                    bf[p][q * 2 + 1][0] = r2; bf[p][q * 2 + 1][1] = r3;
                }
            #pragma unroll
            for (int tm = 0; tm < 4; tm++)
                #pragma unroll
                for (int tn = 0; tn < 4; tn++) {
                    mma_h(acc[tm][tn], af[tm][0], bf[0][tn]);
                    if (BNP == 2) mma_h(acc[tm][tn], af[tm][0], bf[1][tn]);
                    if (ANP == 2) mma_h(acc[tm][tn], af[tm][1], bf[0][tn]);
                }
        }
        __syncthreads();
        if (i + 2 < ns) ldgsts(buf, i + 2);
        if (i + 1 < ns) {
            if (i + 2 < ns) cp_wait<1>(); else cp_wait<0>();
            __syncthreads();
        }
    }

    // ------------------ epilogues ------------------
    if (EPI == 6) {
        float cs[4][2];
        #pragma unroll
        for (int tn = 0; tn < 4; tn++) { cs[tn][0] = 0.f; cs[tn][1] = 0.f; }
        #pragma unroll
        for (int tm = 0; tm < 4; tm++)
            #pragma unroll
            for (int half = 0; half < 2; half++)
                #pragma unroll
                for (int tn = 0; tn < 4; tn++) {
                    cs[tn][0] += __expf(acc[tm][tn][half * 2 + 0] * scale);
                    cs[tn][1] += __expf(acc[tm][tn][half * 2 + 1] * scale);
                }
        float* Zp = Zb + (size_t)zhead * SEQ;
        #pragma unroll
        for (int tn = 0; tn < 4; tn++)
            #pragma unroll
            for (int j = 0; j < 2; j++) {
                float v = cs[tn][j];
                v += __shfl_xor_sync(0xffffffffu, v, 4);
                v += __shfl_xor_sync(0xffffffffu, v, 8);
                v += __shfl_xor_sync(0xffffffffu, v, 16);
                if (lane < 4) atomicAdd(Zp + bn + n0 + tn * 8 + 2 * tg + j, v);
            }
    } else if (EPI == 4) {
        #pragma unroll
        for (int tn = 0; tn < 4; tn++) {
            const int eg  = bn + n0 + tn * 8 + 2 * tg;
            const int seg = eg >> 10;
            const int hh  = (eg >> 6) & 15;
            const int e   = eg & 63;
            const float* bsel = (seg == 0) ? bias : (seg == 1) ? bias2 : bias3;
            float2 bb = *(const float2*)(bsel + hh * 64 + e);
            #pragma unroll
            for (int tm = 0; tm < 4; tm++)
                #pragma unroll
                for (int half = 0; half < 2; half++) {
                    const int row = bm + m0 + tm * 16 + g + half * 8;
                    float vx = acc[tm][tn][half * 2 + 0] + bb.x;
                    float vy = acc[tm][tn][half * 2 + 1] + bb.y;
                    if (seg == 2) {
                        *(float2*)(g_Vf + ((size_t)hh * SEQ + row) * HDIM + e) =
                            make_float2(vx, vy);
                    } else {
                        __half* O = (seg == 0) ? g_Qsp : g_Ksp;
                        size_t base = (size_t)hh * SEQ * HDIM + (size_t)row * HDIM + e;
                        *(uint32_t*)(O + base) =
                            pkh(__float2half_rn(vx), __float2half_rn(vy));
                    }
                }
        }
    } else if (EPI == 5) {
        __half* Ch = (__half*)Cv + zhead * cZ;
        #pragma unroll
        for (int tn = 0; tn < 4; tn++) {
            const int col = bn + n0 + tn * 8 + 2 * tg;
            float2 bb = *(const float2*)(bias + col);
            #pragma unroll
            for (int tm = 0; tm < 4; tm++)
                #pragma unroll
                for (int half = 0; half < 2; half++) {
                    const int row = bm + m0 + tm * 16 + g + half * 8;
                    float vx = acc[tm][tn][half * 2 + 0] + bb.x;
                    float vy = acc[tm][tn][half * 2 + 1] + bb.y;
                    if (RELU) { vx = fmaxf(vx, 0.f); vy = fmaxf(vy, 0.f); }
                    *(uint32_t*)(Ch + (size_t)row * ldc + col) =
                        pkh(__float2half_rn(vx), __float2half_rn(vy));
                }
        }
    } else {
        float* C = (float*)Cv + zhead * cZ;
        #pragma unroll
        for (int tn = 0; tn < 4; tn++) {
            const int col = bn + n0 + tn * 8 + 2 * tg;
            float2 bb = *(const float2*)(bias + col);
            #pragma unroll
            for (int tm = 0; tm < 4; tm++)
                #pragma unroll
                for (int half = 0; half < 2; half++) {
                    const int row = bm + m0 + tm * 16 + g + half * 8;
                    *(float2*)(C + (size_t)row * ldc + col) =
                        make_float2(acc[tm][tn][half * 2 + 0] + bb.x,
                                    acc[tm][tn][half * 2 + 1] + bb.y);
                }
        }
    }
}

// =====================================================================
// Fused attention (hi-only): O[t, h*64+e] = sum_s exp(Khi[t].Qhi[s]/8) Vhi[e,s]
// Per CTA: 128 t-rows (4 warps x 32 rows), one head; s in 32-slabs,
// double-buffered.  smem: K 2x10240 | stage{0,1} 10240: Q 5120 | V 5120.
// Output: Csp hi plane only.
// =====================================================================
#define FAV_SMEM 40960

__global__ void __launch_bounds__(128, 3)
fav(const __half* __restrict__ Qsp, const __half* __restrict__ Ksp,
    const __half* __restrict__ Vn, __half* __restrict__ Csp)
{
    extern __shared__ __align__(16) unsigned char sm[];
    const uint32_t smb = (uint32_t)__cvta_generic_to_shared(sm);

    const int tid = threadIdx.x;
    const int warp = tid >> 5, lane = tid & 31;
    const int g = lane >> 2, tg = lane & 3;
    const int b3 = (lane >> 3) & 1, b4 = (lane >> 4) & 1;
    const int m0 = warp * 32;

    const int bt = blockIdx.x * 128;
    const int h  = blockIdx.y;

    const __half* Kh = Ksp + (size_t)h * SEQ * HDIM;
    const __half* Qh = Qsp + (size_t)h * SEQ * HDIM;
    const __half* Vh = Vn + (size_t)h * HDIM * SEQ;

    uint32_t aOffK[2], bOffQ[2], bOffV[4];
    #pragma unroll
    for (int tm = 0; tm < 2; tm++)
        aOffK[tm] = ((m0 + tm * 16 + (lane & 7) + b3 * 8) * 40 + b4 * 8) * 2;
    #pragma unroll
    for (int q = 0; q < 2; q++)
        bOffQ[q] = ((q * 16 + (lane & 7) + b4 * 8) * 40 + b3 * 8) * 2;
    #pragma unroll
    for (int q = 0; q < 4; q++)
        bOffV[q] = ((q * 16 + (lane & 7) + b4 * 8) * 40 + b3 * 8) * 2;

    // ---- K tile (once): 2 kslabs x [128 rows x 80B] ----
    #pragma unroll
    for (int j = 0; j < 8; j++) {
        int idx = tid + j * 128;
        int slab = idx >> 9;
        int r = (idx & 511) >> 2;
        int c = idx & 3;
        cp16(smb + slab * 10240 + r * 80 + c * 16,
             Kh + (size_t)(bt + r) * HDIM + slab * 32 + c * 8);
    }
    cp_commit();

    auto ldStage = [&](int st, int s0) {
        const uint32_t base = smb + 20480 + st * 10240;
        #pragma unroll
        for (int j = 0; j < 2; j++) {            // Q: 2 kslabs x [32 x 80B]
            int idx = tid + j * 128;
            int ksl = idx >> 7;
            int r = (idx & 127) >> 2;
            int c = idx & 3;
            cp16(base + ksl * 2560 + r * 80 + c * 16,
                 Qh + (size_t)(s0 + r) * HDIM + ksl * 32 + c * 8);
        }
        #pragma unroll
        for (int j = 0; j < 2; j++) {            // V: [64 e x 80B]
            int idx = tid + j * 128;
            int e = idx >> 2;
            int c = idx & 3;
            cp16(base + 5120 + e * 80 + c * 16,
                 Vh + (size_t)e * SEQ + s0 + c * 8);
        }
        cp_commit();
    };

    float O[2][8][4];
    #pragma unroll
    for (int tm = 0; tm < 2; tm++)
        #pragma unroll
        for (int tn = 0; tn < 8; tn++)
            #pragma unroll
            for (int r = 0; r < 4; r++) O[tm][tn][r] = 0.f;

    const int ns = SEQ / 32;
    ldStage(0, 0);
    ldStage(1, 32);
    cp_wait<1>();
    __syncthreads();

    for (int i = 0; i < ns; i++) {
        const int buf = i & 1;
        const uint32_t stg = smb + 20480 + buf * 10240;

        // ---- MMA1: S[128 x 32] = Khi . Qhi ----
        float S[2][4][4];
        #pragma unroll
        for (int tm = 0; tm < 2; tm++)
            #pragma unroll
            for (int tn = 0; tn < 4; tn++)
                #pragma unroll
                for (int r = 0; r < 4; r++) S[tm][tn][r] = 0.f;

        #pragma unroll
        for (int kk = 0; kk < 4; kk++) {
            const int j = kk >> 1, ksl = kk & 1;
            uint32_t aK[2][4], bq[4][2];
            #pragma unroll
            for (int tm = 0; tm < 2; tm++)
                ldsm4(aK[tm][0], aK[tm][1], aK[tm][2], aK[tm][3],
                      smb + j * 10240 + aOffK[tm] + ksl * 32);
            #pragma unroll
            for (int q = 0; q < 2; q++) {
                uint32_t r0, r1, r2, r3;
                ldsm4(r0, r1, r2, r3, stg + j * 2560 + bOffQ[q] + ksl * 32);
                bq[q * 2 + 0][0] = r0; bq[q * 2 + 0][1] = r1;
                bq[q * 2 + 1][0] = r2; bq[q * 2 + 1][1] = r3;
            }
            #pragma unroll
            for (int tm = 0; tm < 2; tm++)
                #pragma unroll
                for (int tn = 0; tn < 4; tn++)
                    mma_h(S[tm][tn], aK[tm], bq[tn]);
        }

        // ---- exp + MMA2: O += P . Vhi ----
        #pragma unroll
        for (int kk2 = 0; kk2 < 2; kk2++) {
            uint32_t pa[2][4];
            #pragma unroll
            for (int tm = 0; tm < 2; tm++) {
                const int nt0 = 2 * kk2, nt1 = nt0 + 1;
                pa[tm][0] = pkh(__float2half_rn(__expf(S[tm][nt0][0] * 0.125f)),
                                __float2half_rn(__expf(S[tm][nt0][1] * 0.125f)));
                pa[tm][1] = pkh(__float2half_rn(__expf(S[tm][nt0][2] * 0.125f)),
                                __float2half_rn(__expf(S[tm][nt0][3] * 0.125f)));
                pa[tm][2] = pkh(__float2half_rn(__expf(S[tm][nt1][0] * 0.125f)),
                                __float2half_rn(__expf(S[tm][nt1][1] * 0.125f)));
                pa[tm][3] = pkh(__float2half_rn(__expf(S[tm][nt1][2] * 0.125f)),
                                __float2half_rn(__expf(S[tm][nt1][3] * 0.125f)));
            }
            #pragma unroll
            for (int q = 0; q < 4; q++) {
                uint32_t r0, r1, r2, r3;
                ldsm4(r0, r1, r2, r3, stg + 5120 + bOffV[q] + kk2 * 32);
                uint32_t bv0[2] = {r0, r1};
                uint32_t bv1[2] = {r2, r3};
                #pragma unroll
                for (int tm = 0; tm < 2; tm++) {
                    mma_h(O[tm][q * 2 + 0], pa[tm], bv0);
                    mma_h(O[tm][q * 2 + 1], pa[tm], bv1);
                }
            }
        }

        __syncthreads();
        if (i + 2 < ns) ldStage(buf, (i + 2) * 32);
        if (i + 1 < ns) {
            if (i + 2 < ns) cp_wait<1>(); else cp_wait<0>();
            __syncthreads();
        }
    }

    // ---- epilogue: Csp hi plane only, col = h*64 + e ----
    #pragma unroll
    for (int tm = 0; tm < 2; tm++)
        #pragma unroll
        for (int tn = 0; tn < 8; tn++) {
            const int col = h * 64 + tn * 8 + 2 * tg;
            #pragma unroll
            for (int half = 0; half < 2; half++) {
                const int row = bt + m0 + tm * 16 + g + half * 8;
                *(uint32_t*)(Csp + (size_t)row * DM + col) =
                    pkh(__float2half_rn(O[tm][tn][half * 2 + 0]),
                        __float2half_rn(O[tm][tn][half * 2 + 1]));
            }
        }
}

// =====================================================================
// prep / glue kernels
// =====================================================================
// x fp32 -> fp16 hi plane only
__global__ void splitf(const float* __restrict__ in, __half* __restrict__ out, size_t n)
{
    size_t i = (size_t)blockIdx.x * blockDim.x + threadIdx.x;
    if (i < n) out[i] = __float2half_rn(in[i]);
}

// W fp32 [K][N] -> fp16 hi plane [N][K].  Tile 64(k) x 32(n), half2 stores.
__global__ void tspw(const float* __restrict__ W, __half* __restrict__ O, int K, int N)
{
    __shared__ float t[64][33];
    const int n0 = blockIdx.x * 32, k0 = blockIdx.y * 64;
    const int tx = threadIdx.x, ty = threadIdx.y;
    const int tid = ty * 32 + tx;
    #pragma unroll
    for (int i = 0; i < 64; i += 8)
        t[ty + i][tx] = W[(size_t)(k0 + ty + i) * N + n0 + tx];
    __syncthreads();
    #pragma unroll
    for (int it = 0; it < 4; it++) {
        int idx = tid + it * 256;
        int c = idx & 31, r = idx >> 5;
        *(uint32_t*)(O + (size_t)(n0 + r) * K + k0 + 2 * c) =
            pkh(__float2half_rn(t[2 * c][r]), __float2half_rn(t[2 * c + 1][r]));
    }
}

// fused QKV weight transpose (hi plane only): z = which*NH + head.
// Tile 64(k) x 32(n) of Wsel[head]: [DM][HDIM] -> rows rowOff+n of [NQKV][DM].
__global__ void tspw_qkv(const float* __restrict__ Wq, const float* __restrict__ Wk,
                         const float* __restrict__ Wv, __half* __restrict__ O)
{
    __shared__ float t[64][33];
    const int z = blockIdx.z;
    const int which = z >> 4, hh = z & 15;
    const float* Wsel = (which == 0) ? Wq : (which == 1) ? Wk : Wv;
    const float* Wb = Wsel + (size_t)hh * DM * HDIM;
    const int n0 = blockIdx.x * 32, k0 = blockIdx.y * 64;
    const int tx = threadIdx.x, ty = threadIdx.y;
    const int tid = ty * 32 + tx;
    #pragma unroll
    for (int i = 0; i < 64; i += 8)
        t[ty + i][tx] = Wb[(size_t)(k0 + ty + i) * HDIM + n0 + tx];
    __syncthreads();
    const int rowOff = which * 1024 + hh * 64;
    #pragma unroll
    for (int it = 0; it < 4; it++) {
        int idx = tid + it * 256;
        int c = idx & 31, r = idx >> 5;
        *(uint32_t*)(O + (size_t)(rowOff + n0 + r) * DM + k0 + 2 * c) =
            pkh(__float2half_rn(t[2 * c][r]), __float2half_rn(t[2 * c + 1][r]));
    }
}

// Vn[h][e][s] = fp16(Vf[h][s][e] / Z[h][s])  (hi plane only; 1/Z inline)
__global__ void rescaleV(const float* __restrict__ Vf, const float* __restrict__ Zz,
                         __half* __restrict__ Vn)
{
    __shared__ float t[32][33];
    const int h = blockIdx.z;
    const int e0 = blockIdx.x * 32, s0 = blockIdx.y * 32;
    const int tx = threadIdx.x, ty = threadIdx.y;
    const float* Vb = Vf + (size_t)h * SEQ * HDIM;
    const float* Zp = Zz + (size_t)h * SEQ;
    #pragma unroll
    for (int i = 0; i < 32; i += 8) {
        int s = s0 + ty + i;
        t[ty + i][tx] = Vb[(size_t)s * HDIM + e0 + tx] * (1.f / Zp[s]);
    }
    __syncthreads();
    __half* Ob = Vn + (size_t)h * HDIM * SEQ;
    #pragma unroll
    for (int i = 0; i < 32; i += 8) {
        size_t o = (size_t)(e0 + ty + i) * SEQ + s0 + tx;
        Ob[o] = __float2half_rn(t[tx][ty + i]);
    }
}

__global__ void zerok(float* __restrict__ p, int n)
{
    int i = blockIdx.x * blockDim.x + threadIdx.x;
    if (i < n) p[i] = 0.f;
}

// =====================================================================
extern "C" void kernel_launch(void* const* d_in, const int* in_sizes, int n_in,
                              void* d_out, int out_size)
{
    const float* x  = (const float*)d_in[0];
    const float* Wq = (const float*)d_in[1];
    const float* bq = (const float*)d_in[2];
    const float* Wk = (const float*)d_in[3];
    const float* bk = (const float*)d_in[4];
    const float* Wv = (const float*)d_in[5];
    const float* bv = (const float*)d_in[6];
    const float* Wp = (const float*)d_in[7];
    const float* bp = (const float*)d_in[8];
    const float* W1 = (const float*)d_in[9];
    const float* b1 = (const float*)d_in[10];
    const float* W2 = (const float*)d_in[11];
    const float* b2 = (const float*)d_in[12];
    float* out = (float*)d_out;

    __half *Xsp, *Wqkvt, *Wpt, *W1t, *W2t, *Qsp, *Ksp, *Vn, *Csp, *Projsp, *Hsp;
    float *Vf, *Z;
    cudaGetSymbolAddress((void**)&Xsp,    g_Xsp);
    cudaGetSymbolAddress((void**)&Wqkvt,  g_Wqkvt);
    cudaGetSymbolAddress((void**)&Wpt,    g_Wpt);
    cudaGetSymbolAddress((void**)&W1t,    g_W1t);
    cudaGetSymbolAddress((void**)&W2t,    g_W2t);
    cudaGetSymbolAddress((void**)&Qsp,    g_Qsp);
    cudaGetSymbolAddress((void**)&Ksp,    g_Ksp);
    cudaGetSymbolAddress((void**)&Vf,     g_Vf);
    cudaGetSymbolAddress((void**)&Vn,     g_Vn);
    cudaGetSymbolAddress((void**)&Z,      g_Z);
    cudaGetSymbolAddress((void**)&Csp,    g_Csp);
    cudaGetSymbolAddress((void**)&Projsp, g_Projsp);
    cudaGetSymbolAddress((void**)&Hsp,    g_Hsp);

    const int SM_11 = 2 * (1 * 10240 + 1 * 128 * 80);  // 40960 (ANP1,BNP1)
    cudaFuncSetAttribute(gg<4,1,1,0,0,4>, cudaFuncAttributeMaxDynamicSharedMemorySize, SM_11);
    cudaFuncSetAttribute(gg<6,1,1,0,0,4>, cudaFuncAttributeMaxDynamicSharedMemorySize, SM_11);
    cudaFuncSetAttribute(gg<5,1,1,0,0,4>, cudaFuncAttributeMaxDynamicSharedMemorySize, SM_11);
    cudaFuncSetAttribute(gg<5,1,1,1,0,4>, cudaFuncAttributeMaxDynamicSharedMemorySize, SM_11);
    cudaFuncSetAttribute(gg<0,1,1,0,0,4>, cudaFuncAttributeMaxDynamicSharedMemorySize, SM_11);
    cudaFuncSetAttribute(fav, cudaFuncAttributeMaxDynamicSharedMemorySize, FAV_SMEM);

    dim3 tb(32, 8);
    // prep (all weight planes hi-only now)
    splitf<<<(SEQ * DM + 255) / 256, 256>>>(x, Xsp, (size_t)SEQ * DM);
    tspw_qkv<<<dim3(2, 16, NH * 3), tb>>>(Wq, Wk, Wv, Wqkvt);
    tspw<<<dim3(32, 16, 1), tb>>>(Wp, Wpt, DM, DM);
    tspw<<<dim3(128, 16, 1), tb>>>(W1, W1t, DM, FFD);
    tspw<<<dim3(32, 64, 1), tb>>>(W2, W2t, FFD, DM);
    zerok<<<(NH * SEQ + 255) / 256, 256>>>(Z, NH * SEQ);

    // 1) fused QKV  (x hi-only, Wqkv hi-only: 1 MMA; Q/K hi-only, V fp32)
    gg<4,1,1,0,0,4><<<dim3(NQKV / 128, SEQ / 128, 1), 256, SM_11>>>(
        Xsp, Wqkvt, bq, bk, bv, nullptr, nullptr,
        DM, DM, DM, 0, 0, 0, 0, 0, 0, 0, 1.f);

    // 2) Z pass: Z[h,s] = sum_t exp(Khi[t].Qhi[s]/8)
    gg<6,1,1,0,0,4><<<dim3(SEQ / 128, SEQ / 128, NH), 256, SM_11>>>(
        Ksp, Qsp, nullptr, nullptr, nullptr, nullptr, Z,
        HDIM, HDIM, HDIM, SEQ,
        (size_t)SEQ * HDIM, (size_t)SEQ * HDIM, 0,
        0, 0, 0, 0.125f);

    // 3) Vn = fp16(V/Z) transposed, hi-only (1/Z inline)
    rescaleV<<<dim3(2, 64, NH), tb>>>(Vf, Z, Vn);

    // 4) fused attention (hi-only, 128-t CTAs): Csp hi plane out
    fav<<<dim3(SEQ / 128, NH), 128, FAV_SMEM>>>(Qsp, Ksp, Vn, Csp);

    // 5) proj = concat @ Wp + bp  (1 MMA; fp16 hi out)
    gg<5,1,1,0,0,4><<<dim3(DM / 128, SEQ / 128, 1), 256, SM_11>>>(
        Csp, Wpt, bp, nullptr, nullptr, Projsp, nullptr,
        DM, DM, DM, DM, 0, 0, 0,
        0, 0, 0, 1.f);

    // 6) hidden = relu(proj @ W1 + b1)  (1 MMA)
    gg<5,1,1,1,0,4><<<dim3(FFD / 128, SEQ / 128, 1), 256, SM_11>>>(
        Projsp, W1t, b1, nullptr, nullptr, Hsp, nullptr,
        DM, DM, DM, FFD, 0, 0, 0,
        0, 0, 0, 1.f);

    // 7) out = hidden @ W2 + b2  (1 MMA)
    gg<0,1,1,0,0,4><<<dim3(DM / 128, SEQ / 128, 1), 256, SM_11>>>(
        Hsp, W2t, b2, nullptr, nullptr, out, nullptr,
        FFD, FFD, FFD, DM, 0, 0, 0,
        0, 0, 0, 1.f);
}

// round 17
// speedup vs baseline: 1.1853x; 1.0565x over previous
#include <cuda_runtime.h>
#include <cuda_fp16.h>
#include <cstdint>

#define SEQ  2048
#define DM   1024
#define NH   16
#define HDIM 64
#define FFD  4096
#define NQKV 3072

// ---------------- scratch (no allocations allowed) ----------------
__device__ __half g_Xsp[(size_t)SEQ * DM];      // hi plane only
__device__ __half g_Wqkvt[(size_t)NQKV * DM];   // hi plane only
__device__ __half g_Wpt[(size_t)DM * DM];       // hi plane only
__device__ __half g_W1t[(size_t)FFD * DM];      // hi plane only
__device__ __half g_W2t[(size_t)DM * FFD];      // hi plane only
__device__ __half g_Qsp[NH * SEQ * HDIM];       // hi plane only
__device__ __half g_Ksp[NH * SEQ * HDIM];       // hi plane only
__device__ float  g_Vf[NH * SEQ * HDIM];
__device__ __half g_Vn[NH * HDIM * SEQ];        // hi plane only
__device__ float  g_Z[NH * SEQ];
__device__ __half g_Csp[(size_t)SEQ * DM];      // hi plane only
__device__ __half g_Projsp[(size_t)SEQ * DM];   // hi plane only
__device__ __half g_Hsp[(size_t)SEQ * FFD];     // hi plane only

// ---------------- helpers ----------------
__device__ __forceinline__ uint32_t pkh(__half a, __half b) {
    __half2 t(a, b);
    return *reinterpret_cast<uint32_t*>(&t);
}
__device__ __forceinline__ void ldsm4(uint32_t& r0, uint32_t& r1, uint32_t& r2, uint32_t& r3, uint32_t a) {
    asm volatile("ldmatrix.sync.aligned.m8n8.x4.shared.b16 {%0,%1,%2,%3}, [%4];"
                 : "=r"(r0), "=r"(r1), "=r"(r2), "=r"(r3) : "r"(a));
}
__device__ __forceinline__ void mma_h(float c[4], const uint32_t a[4], const uint32_t b[2]) {
    asm volatile(
        "mma.sync.aligned.m16n8k16.row.col.f32.f16.f16.f32 "
        "{%0,%1,%2,%3}, {%4,%5,%6,%7}, {%8,%9}, {%0,%1,%2,%3};"
        : "+f"(c[0]), "+f"(c[1]), "+f"(c[2]), "+f"(c[3])
        : "r"(a[0]), "r"(a[1]), "r"(a[2]), "r"(a[3]), "r"(b[0]), "r"(b[1]));
}
__device__ __forceinline__ void cp16(uint32_t dst, const void* src) {
    asm volatile("cp.async.cg.shared.global [%0], [%1], 16;" :: "r"(dst), "l"(src));
}
__device__ __forceinline__ void cp_commit() {
    asm volatile("cp.async.commit_group;" ::: "memory");
}
template <int N>
__device__ __forceinline__ void cp_wait() {
    asm volatile("cp.async.wait_group %0;" :: "n"(N) : "memory");
}

// =====================================================================
// fp16 mma.sync GEMM.  CTA 128(M) x 32*NW2(N), BK=32, 3-stage cp.async
// pipeline (one __syncthreads per iteration).
// ANP/BNP: number of A/B fp16 planes.
// EPI: 0 fp32+bias, 4 QKV scatter (Q/K hi-only, V fp32),
//      5 fp16 hi-only out+bias(+relu), 6 exp -> col-Z atomics (no store).
// =====================================================================
template <int EPI, int ANP, int BNP, int RELU, int SKBITS, int NW2>
__global__ void __launch_bounds__(NW2 * 64, (NW2 == 2) ? 3 : 2)
gg(const __half* __restrict__ A, const __half* __restrict__ B,
   const float* __restrict__ bias, const float* __restrict__ bias2,
   const float* __restrict__ bias3, void* __restrict__ Cv,
   float* __restrict__ Zb,
   int K, int lda, int ldb, int ldc,
   size_t aZ, size_t bZ, size_t cZ, size_t pA, size_t pB, size_t pC,
   float scale)
{
    constexpr int T     = NW2 * 64;
    constexpr int BNT   = 32 * NW2;
    constexpr int ASEG_ = 10240;
    constexpr int BSEG_ = BNT * 80;
    constexpr int STG   = ANP * ASEG_ + BNP * BSEG_;
    constexpr int CA    = 512 / T;

    extern __shared__ __align__(16) unsigned char sm[];
    const uint32_t smb = (uint32_t)__cvta_generic_to_shared(sm);

    const int tid = threadIdx.x;
    const int warp = tid >> 5, lane = tid & 31;
    const int g = lane >> 2, tg = lane & 3;
    const int b3 = (lane >> 3) & 1, b4 = (lane >> 4) & 1;
    const int m0 = (warp & 1) * 64, n0 = (warp >> 1) * 32;

    const int z = blockIdx.z;
    const int zhead = z >> SKBITS;
    const int bm = blockIdx.y * 128;
    const int bn = blockIdx.x * BNT;

    const __half* Ag = A + zhead * aZ;
    const __half* Bg = B + zhead * bZ;

    uint32_t aOff[4], bOff[2];
    #pragma unroll
    for (int tm = 0; tm < 4; tm++)
        aOff[tm] = ((m0 + tm * 16 + (lane & 7) + b3 * 8) * 40 + b4 * 8) * 2;
    #pragma unroll
    for (int q = 0; q < 2; q++)
        bOff[q] = ((n0 + q * 16 + (lane & 7) + b4 * 8) * 40 + b3 * 8) * 2;

    auto ldgsts = [&](int st, int slab) {
        const int k0 = slab << 5;
        #pragma unroll
        for (int p = 0; p < ANP; p++)
            #pragma unroll
            for (int j = 0; j < CA; j++) {
                int idx = tid + j * T;
                int row = idx >> 2, kc = idx & 3;
                cp16(smb + st * STG + p * ASEG_ + row * 80 + kc * 16,
                     Ag + p * pA + (size_t)(bm + row) * lda + k0 + kc * 8);
            }
        #pragma unroll
        for (int p = 0; p < BNP; p++)
            #pragma unroll
            for (int j = 0; j < 2; j++) {
                int idx = tid + j * T;
                int row = idx >> 2, kc = idx & 3;
                cp16(smb + st * STG + ANP * ASEG_ + p * BSEG_ + row * 80 + kc * 16,
                     Bg + p * pB + (size_t)(bn + row) * ldb + k0 + kc * 8);
            }
        cp_commit();
    };

    float acc[4][4][4];
    #pragma unroll
    for (int tm = 0; tm < 4; tm++)
        #pragma unroll
        for (int tn = 0; tn < 4; tn++)
            #pragma unroll
            for (int r = 0; r < 4; r++) acc[tm][tn][r] = 0.f;

    const int ns = K >> 5;
    ldgsts(0, 0);
    ldgsts(1, 1);
    cp_wait<1>();
    __syncthreads();

    int buf = 0;
    for (int i = 0; i < ns; i++) {
        if (i + 2 < ns) {
            int st = buf + 2; if (st >= 3) st -= 3;
            ldgsts(st, i + 2);
        }
        const uint32_t aB = smb + buf * STG;
        const uint32_t bB = smb + buf * STG + ANP * ASEG_;
        #pragma unroll
        for (int ks = 0; ks < 2; ks++) {
            uint32_t af[4][ANP][4], bf[BNP][4][2];
            #pragma unroll
            for (int tm = 0; tm < 4; tm++)
                #pragma unroll
                for (int p = 0; p < ANP; p++)
                    ldsm4(af[tm][p][0], af[tm][p][1], af[tm][p][2], af[tm][p][3],
                          aB + p * ASEG_ + aOff[tm] + ks * 32);
            #pragma unroll
            for (int p = 0; p < BNP; p++)
                #pragma unroll
                for (int q = 0; q < 2; q++) {
                    uint32_t r0, r1, r2, r3;
                    ldsm4(r0, r1, r2, r3, bB + p * BSEG_ + bOff[q] + ks * 32);
                    bf[p][q * 2 + 0][0] = r0; bf[p][q * 2 + 0][1] = r1;
                    bf[p][q * 2 + 1][0] = r2; bf[p][q * 2 + 1][1] = r3;
                }
            #pragma unroll
            for (int tm = 0; tm < 4; tm++)
                #pragma unroll
                for (int tn = 0; tn < 4; tn++) {
                    mma_h(acc[tm][tn], af[tm][0], bf[0][tn]);
                    if (BNP == 2) mma_h(acc[tm][tn], af[tm][0], bf[1][tn]);
                    if (ANP == 2) mma_h(acc[tm][tn], af[tm][1], bf[0][tn]);
                }
        }
        if (i + 2 < ns) cp_wait<1>(); else cp_wait<0>();
        __syncthreads();
        if (++buf == 3) buf = 0;
    }

    // ------------------ epilogues ------------------
    if (EPI == 6) {
        float cs[4][2];
        #pragma unroll
        for (int tn = 0; tn < 4; tn++) { cs[tn][0] = 0.f; cs[tn][1] = 0.f; }
        #pragma unroll
        for (int tm = 0; tm < 4; tm++)
            #pragma unroll
            for (int half = 0; half < 2; half++)
                #pragma unroll
                for (int tn = 0; tn < 4; tn++) {
                    cs[tn][0] += __expf(acc[tm][tn][half * 2 + 0] * scale);
                    cs[tn][1] += __expf(acc[tm][tn][half * 2 + 1] * scale);
                }
        float* Zp = Zb + (size_t)zhead * SEQ;
        #pragma unroll
        for (int tn = 0; tn < 4; tn++)
            #pragma unroll
            for (int j = 0; j < 2; j++) {
                float v = cs[tn][j];
                v += __shfl_xor_sync(0xffffffffu, v, 4);
                v += __shfl_xor_sync(0xffffffffu, v, 8);
                v += __shfl_xor_sync(0xffffffffu, v, 16);
                if (lane < 4) atomicAdd(Zp + bn + n0 + tn * 8 + 2 * tg + j, v);
            }
    } else if (EPI == 4) {
        #pragma unroll
        for (int tn = 0; tn < 4; tn++) {
            const int eg  = bn + n0 + tn * 8 + 2 * tg;
            const int seg = eg >> 10;
            const int hh  = (eg >> 6) & 15;
            const int e   = eg & 63;
            const float* bsel = (seg == 0) ? bias : (seg == 1) ? bias2 : bias3;
            float2 bb = *(const float2*)(bsel + hh * 64 + e);
            #pragma unroll
            for (int tm = 0; tm < 4; tm++)
                #pragma unroll
                for (int half = 0; half < 2; half++) {
                    const int row = bm + m0 + tm * 16 + g + half * 8;
                    float vx = acc[tm][tn][half * 2 + 0] + bb.x;
                    float vy = acc[tm][tn][half * 2 + 1] + bb.y;
                    if (seg == 2) {
                        *(float2*)(g_Vf + ((size_t)hh * SEQ + row) * HDIM + e) =
                            make_float2(vx, vy);
                    } else {
                        __half* O = (seg == 0) ? g_Qsp : g_Ksp;
                        size_t base = (size_t)hh * SEQ * HDIM + (size_t)row * HDIM + e;
                        *(uint32_t*)(O + base) =
                            pkh(__float2half_rn(vx), __float2half_rn(vy));
                    }
                }
        }
    } else if (EPI == 5) {
        __half* Ch = (__half*)Cv + zhead * cZ;
        #pragma unroll
        for (int tn = 0; tn < 4; tn++) {
            const int col = bn + n0 + tn * 8 + 2 * tg;
            float2 bb = *(const float2*)(bias + col);
            #pragma unroll
            for (int tm = 0; tm < 4; tm++)
                #pragma unroll
                for (int half = 0; half < 2; half++) {
                    const int row = bm + m0 + tm * 16 + g + half * 8;
                    float vx = acc[tm][tn][half * 2 + 0] + bb.x;
                    float vy = acc[tm][tn][half * 2 + 1] + bb.y;
                    if (RELU) { vx = fmaxf(vx, 0.f); vy = fmaxf(vy, 0.f); }
                    *(uint32_t*)(Ch + (size_t)row * ldc + col) =
                        pkh(__float2half_rn(vx), __float2half_rn(vy));
                }
        }
    } else {
        float* C = (float*)Cv + zhead * cZ;
        #pragma unroll
        for (int tn = 0; tn < 4; tn++) {
            const int col = bn + n0 + tn * 8 + 2 * tg;
            float2 bb = *(const float2*)(bias + col);
            #pragma unroll
            for (int tm = 0; tm < 4; tm++)
                #pragma unroll
                for (int half = 0; half < 2; half++) {
                    const int row = bm + m0 + tm * 16 + g + half * 8;
                    *(float2*)(C + (size_t)row * ldc + col) =
                        make_float2(acc[tm][tn][half * 2 + 0] + bb.x,
                                    acc[tm][tn][half * 2 + 1] + bb.y);
                }
        }
    }
}

// =====================================================================
// Fused attention (hi-only): O[t, h*64+e] = sum_s exp(Khi[t].Qhi[s]/8) Vhi[e,s]
// Per CTA: 128 t-rows, one head; s in 32-slabs, 3-stage cp.async
// pipeline (one sync per iteration).
// smem: K 2x10240 | stage{0..2} 10240 each: Q 5120 | V 5120.
// Output: Csp hi plane only.
// =====================================================================
#define FAV_SMEM 51200

__global__ void __launch_bounds__(128, 3)
fav(const __half* __restrict__ Qsp, const __half* __restrict__ Ksp,
    const __half* __restrict__ Vn, __half* __restrict__ Csp)
{
    extern __shared__ __align__(16) unsigned char sm[];
    const uint32_t smb = (uint32_t)__cvta_generic_to_shared(sm);

    const int tid = threadIdx.x;
    const int warp = tid >> 5, lane = tid & 31;
    const int g = lane >> 2, tg = lane & 3;
    const int b3 = (lane >> 3) & 1, b4 = (lane >> 4) & 1;
    const int m0 = warp * 32;

    const int bt = blockIdx.x * 128;
    const int h  = blockIdx.y;

    const __half* Kh = Ksp + (size_t)h * SEQ * HDIM;
    const __half* Qh = Qsp + (size_t)h * SEQ * HDIM;
    const __half* Vh = Vn + (size_t)h * HDIM * SEQ;

    uint32_t aOffK[2], bOffQ[2], bOffV[4];
    #pragma unroll
    for (int tm = 0; tm < 2; tm++)
        aOffK[tm] = ((m0 + tm * 16 + (lane & 7) + b3 * 8) * 40 + b4 * 8) * 2;
    #pragma unroll
    for (int q = 0; q < 2; q++)
        bOffQ[q] = ((q * 16 + (lane & 7) + b4 * 8) * 40 + b3 * 8) * 2;
    #pragma unroll
    for (int q = 0; q < 4; q++)
        bOffV[q] = ((q * 16 + (lane & 7) + b4 * 8) * 40 + b3 * 8) * 2;

    // ---- K tile (once): 2 kslabs x [128 rows x 80B] ----
    #pragma unroll
    for (int j = 0; j < 8; j++) {
        int idx = tid + j * 128;
        int slab = idx >> 9;
        int r = (idx & 511) >> 2;
        int c = idx & 3;
        cp16(smb + slab * 10240 + r * 80 + c * 16,
             Kh + (size_t)(bt + r) * HDIM + slab * 32 + c * 8);
    }
    cp_commit();

    auto ldStage = [&](int st, int s0) {
        const uint32_t base = smb + 20480 + st * 10240;
        #pragma unroll
        for (int j = 0; j < 2; j++) {            // Q: 2 kslabs x [32 x 80B]
            int idx = tid + j * 128;
            int ksl = idx >> 7;
            int r = (idx & 127) >> 2;
            int c = idx & 3;
            cp16(base + ksl * 2560 + r * 80 + c * 16,
                 Qh + (size_t)(s0 + r) * HDIM + ksl * 32 + c * 8);
        }
        #pragma unroll
        for (int j = 0; j < 2; j++) {            // V: [64 e x 80B]
            int idx = tid + j * 128;
            int e = idx >> 2;
            int c = idx & 3;
            cp16(base + 5120 + e * 80 + c * 16,
                 Vh + (size_t)e * SEQ + s0 + c * 8);
        }
        cp_commit();
    };

    float O[2][8][4];
    #pragma unroll
    for (int tm = 0; tm < 2; tm++)
        #pragma unroll
        for (int tn = 0; tn < 8; tn++)
            #pragma unroll
            for (int r = 0; r < 4; r++) O[tm][tn][r] = 0.f;

    const int ns = SEQ / 32;
    ldStage(0, 0);
    ldStage(1, 32);
    cp_wait<1>();      // K + stage0 ready; stage1 in flight
    __syncthreads();

    int buf = 0;
    for (int i = 0; i < ns; i++) {
        if (i + 2 < ns) {
            int st = buf + 2; if (st >= 3) st -= 3;
            ldStage(st, (i + 2) * 32);
        }
        const uint32_t stg = smb + 20480 + buf * 10240;

        // ---- MMA1: S[128 x 32] = Khi . Qhi ----
        float S[2][4][4];
        #pragma unroll
        for (int tm = 0; tm < 2; tm++)
            #pragma unroll
            for (int tn = 0; tn < 4; tn++)
                #pragma unroll
                for (int r = 0; r < 4; r++) S[tm][tn][r] = 0.f;

        #pragma unroll
        for (int kk = 0; kk < 4; kk++) {
            const int j = kk >> 1, ksl = kk & 1;
            uint32_t aK[2][4], bq[4][2];
            #pragma unroll
            for (int tm = 0; tm < 2; tm++)
                ldsm4(aK[tm][0], aK[tm][1], aK[tm][2], aK[tm][3],
                      smb + j * 10240 + aOffK[tm] + ksl * 32);
            #pragma unroll
            for (int q = 0; q < 2; q++) {
                uint32_t r0, r1, r2, r3;
                ldsm4(r0, r1, r2, r3, stg + j * 2560 + bOffQ[q] + ksl * 32);
                bq[q * 2 + 0][0] = r0; bq[q * 2 + 0][1] = r1;
                bq[q * 2 + 1][0] = r2; bq[q * 2 + 1][1] = r3;
            }
            #pragma unroll
            for (int tm = 0; tm < 2; tm++)
                #pragma unroll
                for (int tn = 0; tn < 4; tn++)
                    mma_h(S[tm][tn], aK[tm], bq[tn]);
        }

        // ---- exp + MMA2: O += P . Vhi ----
        #pragma unroll
        for (int kk2 = 0; kk2 < 2; kk2++) {
            uint32_t pa[2][4];
            #pragma unroll
            for (int tm = 0; tm < 2; tm++) {
                const int nt0 = 2 * kk2, nt1 = nt0 + 1;
                pa[tm][0] = pkh(__float2half_rn(__expf(S[tm][nt0][0] * 0.125f)),
                                __float2half_rn(__expf(S[tm][nt0][1] * 0.125f)));
                pa[tm][1] = pkh(__float2half_rn(__expf(S[tm][nt0][2] * 0.125f)),
                                __float2half_rn(__expf(S[tm][nt0][3] * 0.125f)));
                pa[tm][2] = pkh(__float2half_rn(__expf(S[tm][nt1][0] * 0.125f)),
                                __float2half_rn(__expf(S[tm][nt1][1] * 0.125f)));
                pa[tm][3] = pkh(__float2half_rn(__expf(S[tm][nt1][2] * 0.125f)),
                                __float2half_rn(__expf(S[tm][nt1][3] * 0.125f)));
            }
            #pragma unroll
            for (int q = 0; q < 4; q++) {
                uint32_t r0, r1, r2, r3;
                ldsm4(r0, r1, r2, r3, stg + 5120 + bOffV[q] + kk2 * 32);
                uint32_t bv0[2] = {r0, r1};
                uint32_t bv1[2] = {r2, r3};
                #pragma unroll
                for (int tm = 0; tm < 2; tm++) {
                    mma_h(O[tm][q * 2 + 0], pa[tm], bv0);
                    mma_h(O[tm][q * 2 + 1], pa[tm], bv1);
                }
            }
        }

        if (i + 2 < ns) cp_wait<1>(); else cp_wait<0>();
        __syncthreads();
        if (++buf == 3) buf = 0;
    }

    // ---- epilogue: Csp hi plane only, col = h*64 + e ----
    #pragma unroll
    for (int tm = 0; tm < 2; tm++)
        #pragma unroll
        for (int tn = 0; tn < 8; tn++) {
            const int col = h * 64 + tn * 8 + 2 * tg;
            #pragma unroll
            for (int half = 0; half < 2; half++) {
                const int row = bt + m0 + tm * 16 + g + half * 8;
                *(uint32_t*)(Csp + (size_t)row * DM + col) =
                    pkh(__float2half_rn(O[tm][tn][half * 2 + 0]),
                        __float2half_rn(O[tm][tn][half * 2 + 1]));
            }
        }
}

// =====================================================================
// prep / glue kernels
// =====================================================================
// x fp32 -> fp16 hi plane only
__global__ void splitf(const float* __restrict__ in, __half* __restrict__ out, size_t n)
{
    size_t i = (size_t)blockIdx.x * blockDim.x + threadIdx.x;
    if (i < n) out[i] = __float2half_rn(in[i]);
}

// W fp32 [K][N] -> fp16 hi plane [N][K].  Tile 64(k) x 32(n), half2 stores.
__global__ void tspw(const float* __restrict__ W, __half* __restrict__ O, int K, int N)
{
    __shared__ float t[64][33];
    const int n0 = blockIdx.x * 32, k0 = blockIdx.y * 64;
    const int tx = threadIdx.x, ty = threadIdx.y;
    const int tid = ty * 32 + tx;
    #pragma unroll
    for (int i = 0; i < 64; i += 8)
        t[ty + i][tx] = W[(size_t)(k0 + ty + i) * N + n0 + tx];
    __syncthreads();
    #pragma unroll
    for (int it = 0; it < 4; it++) {
        int idx = tid + it * 256;
        int c = idx & 31, r = idx >> 5;
        *(uint32_t*)(O + (size_t)(n0 + r) * K + k0 + 2 * c) =
            pkh(__float2half_rn(t[2 * c][r]), __float2half_rn(t[2 * c + 1][r]));
    }
}

// fused QKV weight transpose (hi plane only): z = which*NH + head.
__global__ void tspw_qkv(const float* __restrict__ Wq, const float* __restrict__ Wk,
                         const float* __restrict__ Wv, __half* __restrict__ O)
{
    __shared__ float t[64][33];
    const int z = blockIdx.z;
    const int which = z >> 4, hh = z & 15;
    const float* Wsel = (which == 0) ? Wq : (which == 1) ? Wk : Wv;
    const float* Wb = Wsel + (size_t)hh * DM * HDIM;
    const int n0 = blockIdx.x * 32, k0 = blockIdx.y * 64;
    const int tx = threadIdx.x, ty = threadIdx.y;
    const int tid = ty * 32 + tx;
    #pragma unroll
    for (int i = 0; i < 64; i += 8)
        t[ty + i][tx] = Wb[(size_t)(k0 + ty + i) * HDIM + n0 + tx];
    __syncthreads();
    const int rowOff = which * 1024 + hh * 64;
    #pragma unroll
    for (int it = 0; it < 4; it++) {
        int idx = tid + it * 256;
        int c = idx & 31, r = idx >> 5;
        *(uint32_t*)(O + (size_t)(rowOff + n0 + r) * DM + k0 + 2 * c) =
            pkh(__float2half_rn(t[2 * c][r]), __float2half_rn(t[2 * c + 1][r]));
    }
}

// Vn[h][e][s] = fp16(Vf[h][s][e] / Z[h][s])  (hi plane only; 1/Z inline)
__global__ void rescaleV(const float* __restrict__ Vf, const float* __restrict__ Zz,
                         __half* __restrict__ Vn)
{
    __shared__ float t[32][33];
    const int h = blockIdx.z;
    const int e0 = blockIdx.x * 32, s0 = blockIdx.y * 32;
    const int tx = threadIdx.x, ty = threadIdx.y;
    const float* Vb = Vf + (size_t)h * SEQ * HDIM;
    const float* Zp = Zz + (size_t)h * SEQ;
    #pragma unroll
    for (int i = 0; i < 32; i += 8) {
        int s = s0 + ty + i;
        t[ty + i][tx] = Vb[(size_t)s * HDIM + e0 + tx] * (1.f / Zp[s]);
    }
    __syncthreads();
    __half* Ob = Vn + (size_t)h * HDIM * SEQ;
    #pragma unroll
    for (int i = 0; i < 32; i += 8) {
        size_t o = (size_t)(e0 + ty + i) * SEQ + s0 + tx;
        Ob[o] = __float2half_rn(t[tx][ty + i]);
    }
}

__global__ void zerok(float* __restrict__ p, int n)
{
    int i = blockIdx.x * blockDim.x + threadIdx.x;
    if (i < n) p[i] = 0.f;
}

// =====================================================================
extern "C" void kernel_launch(void* const* d_in, const int* in_sizes, int n_in,
                              void* d_out, int out_size)
{
    const float* x  = (const float*)d_in[0];
    const float* Wq = (const float*)d_in[1];
    const float* bq = (const float*)d_in[2];
    const float* Wk = (const float*)d_in[3];
    const float* bk = (const float*)d_in[4];
    const float* Wv = (const float*)d_in[5];
    const float* bv = (const float*)d_in[6];
    const float* Wp = (const float*)d_in[7];
    const float* bp = (const float*)d_in[8];
    const float* W1 = (const float*)d_in[9];
    const float* b1 = (const float*)d_in[10];
    const float* W2 = (const float*)d_in[11];
    const float* b2 = (const float*)d_in[12];
    float* out = (float*)d_out;

    __half *Xsp, *Wqkvt, *Wpt, *W1t, *W2t, *Qsp, *Ksp, *Vn, *Csp, *Projsp, *Hsp;
    float *Vf, *Z;
    cudaGetSymbolAddress((void**)&Xsp,    g_Xsp);
    cudaGetSymbolAddress((void**)&Wqkvt,  g_Wqkvt);
    cudaGetSymbolAddress((void**)&Wpt,    g_Wpt);
    cudaGetSymbolAddress((void**)&W1t,    g_W1t);
    cudaGetSymbolAddress((void**)&W2t,    g_W2t);
    cudaGetSymbolAddress((void**)&Qsp,    g_Qsp);
    cudaGetSymbolAddress((void**)&Ksp,    g_Ksp);
    cudaGetSymbolAddress((void**)&Vf,     g_Vf);
    cudaGetSymbolAddress((void**)&Vn,     g_Vn);
    cudaGetSymbolAddress((void**)&Z,      g_Z);
    cudaGetSymbolAddress((void**)&Csp,    g_Csp);
    cudaGetSymbolAddress((void**)&Projsp, g_Projsp);
    cudaGetSymbolAddress((void**)&Hsp,    g_Hsp);

    const int SM_11 = 3 * (1 * 10240 + 1 * 128 * 80);  // 61440: 3-stage
    cudaFuncSetAttribute(gg<4,1,1,0,0,4>, cudaFuncAttributeMaxDynamicSharedMemorySize, SM_11);
    cudaFuncSetAttribute(gg<6,1,1,0,0,4>, cudaFuncAttributeMaxDynamicSharedMemorySize, SM_11);
    cudaFuncSetAttribute(gg<5,1,1,0,0,4>, cudaFuncAttributeMaxDynamicSharedMemorySize, SM_11);
    cudaFuncSetAttribute(gg<5,1,1,1,0,4>, cudaFuncAttributeMaxDynamicSharedMemorySize, SM_11);
    cudaFuncSetAttribute(gg<0,1,1,0,0,4>, cudaFuncAttributeMaxDynamicSharedMemorySize, SM_11);
    cudaFuncSetAttribute(fav, cudaFuncAttributeMaxDynamicSharedMemorySize, FAV_SMEM);

    dim3 tb(32, 8);
    // prep
    splitf<<<(SEQ * DM + 255) / 256, 256>>>(x, Xsp, (size_t)SEQ * DM);
    tspw_qkv<<<dim3(2, 16, NH * 3), tb>>>(Wq, Wk, Wv, Wqkvt);
    tspw<<<dim3(32, 16, 1), tb>>>(Wp, Wpt, DM, DM);
    tspw<<<dim3(128, 16, 1), tb>>>(W1, W1t, DM, FFD);
    tspw<<<dim3(32, 64, 1), tb>>>(W2, W2t, FFD, DM);
    zerok<<<(NH * SEQ + 255) / 256, 256>>>(Z, NH * SEQ);

    // 1) fused QKV  (1 MMA; Q/K hi-only, V fp32)
    gg<4,1,1,0,0,4><<<dim3(NQKV / 128, SEQ / 128, 1), 256, SM_11>>>(
        Xsp, Wqkvt, bq, bk, bv, nullptr, nullptr,
        DM, DM, DM, 0, 0, 0, 0, 0, 0, 0, 1.f);

    // 2) Z pass: Z[h,s] = sum_t exp(Khi[t].Qhi[s]/8)
    gg<6,1,1,0,0,4><<<dim3(SEQ / 128, SEQ / 128, NH), 256, SM_11>>>(
        Ksp, Qsp, nullptr, nullptr, nullptr, nullptr, Z,
        HDIM, HDIM, HDIM, SEQ,
        (size_t)SEQ * HDIM, (size_t)SEQ * HDIM, 0,
        0, 0, 0, 0.125f);

    // 3) Vn = fp16(V/Z) transposed, hi-only
    rescaleV<<<dim3(2, 64, NH), tb>>>(Vf, Z, Vn);

    // 4) fused attention: Csp hi plane out
    fav<<<dim3(SEQ / 128, NH), 128, FAV_SMEM>>>(Qsp, Ksp, Vn, Csp);

    // 5) proj = concat @ Wp + bp  (1 MMA; fp16 hi out)
    gg<5,1,1,0,0,4><<<dim3(DM / 128, SEQ / 128, 1), 256, SM_11>>>(
        Csp, Wpt, bp, nullptr, nullptr, Projsp, nullptr,
        DM, DM, DM, DM, 0, 0, 0,
        0, 0, 0, 1.f);

    // 6) hidden = relu(proj @ W1 + b1)  (1 MMA)
    gg<5,1,1,1,0,4><<<dim3(FFD / 128, SEQ / 128, 1), 256, SM_11>>>(
        Projsp, W1t, b1, nullptr, nullptr, Hsp, nullptr,
        DM, DM, DM, FFD, 0, 0, 0,
        0, 0, 0, 1.f);

    // 7) out = hidden @ W2 + b2  (1 MMA)
    gg<0,1,1,0,0,4><<<dim3(DM / 128, SEQ / 128, 1), 256, SM_11>>>(
        Hsp, W2t, b2, nullptr, nullptr, out, nullptr,
        FFD, FFD, FFD, DM, 0, 0, 0,
        0, 0, 0, 1.f);
}